// round 1
// baseline (speedup 1.0000x reference)
#include <cuda_runtime.h>

#define NN 50000
#define NF 128
#define NE 600000
#define NR 2

// scratch (device globals: no allocation allowed)
__device__ float g_h[(size_t)NN * NF];
__device__ float g_hn[(size_t)NN * NF];
__device__ float g_sums[(size_t)NN * NR * NF];
__device__ float g_cnt[(size_t)NN * NR];
__device__ float g_stats[2 * NF];

// ---------------------------------------------------------------------------
// Column stats: sum and sumsq per feature (for BatchNorm), atomically reduced
// ---------------------------------------------------------------------------
__global__ void stats_kernel(const float* __restrict__ in) {
    __shared__ float ss[256], sq[256];
    const int tid = threadIdx.x;
    const int f = tid & 127;
    const int half = tid >> 7;
    float s = 0.f, s2 = 0.f;
    for (int r = blockIdx.x * 2 + half; r < NN; r += gridDim.x * 2) {
        float v = in[r * NF + f];
        s += v;
        s2 += v * v;
    }
    ss[tid] = s;
    sq[tid] = s2;
    __syncthreads();
    if (tid < 128) {
        atomicAdd(&g_stats[f], ss[tid] + ss[tid + 128]);
        atomicAdd(&g_stats[NF + f], sq[tid] + sq[tid + 128]);
    }
}

// ---------------------------------------------------------------------------
// BatchNorm normalize: g_hn = (in - mu) * rsqrt(var + eps) + 1e-4
// ---------------------------------------------------------------------------
__global__ void bn_kernel(const float* __restrict__ in) {
    const int i = blockIdx.x * blockDim.x + threadIdx.x;  // float4 index
    const int total = NN * NF / 4;
    if (i >= total) return;
    const int fb = (i * 4) & 127;
    const float4 v = ((const float4*)in)[i];
    const float invn = 1.0f / NN;
    float4 o;
    float mu, var, rs;
    mu = g_stats[fb + 0] * invn; var = g_stats[NF + fb + 0] * invn - mu * mu;
    rs = rsqrtf(var + 1e-5f); o.x = (v.x - mu) * rs + 1e-4f;
    mu = g_stats[fb + 1] * invn; var = g_stats[NF + fb + 1] * invn - mu * mu;
    rs = rsqrtf(var + 1e-5f); o.y = (v.y - mu) * rs + 1e-4f;
    mu = g_stats[fb + 2] * invn; var = g_stats[NF + fb + 2] * invn - mu * mu;
    rs = rsqrtf(var + 1e-5f); o.z = (v.z - mu) * rs + 1e-4f;
    mu = g_stats[fb + 3] * invn; var = g_stats[NF + fb + 3] * invn - mu * mu;
    rs = rsqrtf(var + 1e-5f); o.w = (v.w - mu) * rs + 1e-4f;
    ((float4*)g_hn)[i] = o;
}

// ---------------------------------------------------------------------------
// Edge scatter: one warp per edge. Gathers hn[src] (float4/lane) and
// atomically accumulates into sums[(dst*R + type)*128 + f]; counts per segment.
// ---------------------------------------------------------------------------
__global__ void scatter_kernel(const int* __restrict__ src,
                               const int* __restrict__ dst,
                               const int* __restrict__ et) {
    const int w = (blockIdx.x * blockDim.x + threadIdx.x) >> 5;
    const int lane = threadIdx.x & 31;
    if (w >= NE) return;
    const int s = __ldg(src + w);
    const int d = __ldg(dst + w);
    const int t = __ldg(et + w);
    const float4 v = ((const float4*)g_hn)[(size_t)s * 32 + lane];
    float* base = g_sums + ((size_t)d * NR + t) * NF + lane * 4;
    atomicAdd(base + 0, v.x);
    atomicAdd(base + 1, v.y);
    atomicAdd(base + 2, v.z);
    atomicAdd(base + 3, v.w);
    if (lane == 0) atomicAdd(&g_cnt[(size_t)d * NR + t], 1.0f);
}

// ---------------------------------------------------------------------------
// Fused GEMM: out[n,h] = relu( sum_k A[n,k] * B[k,h] + bias[h] ) (+ res[n,h])
//   A[n, k<256]   = sums[n,k] / max(cnt[n, k>>7], 1)   (per-relation mean)
//   A[n, 256+d]   = hn[n,d]                            (root term)
//   B[k<256, h]   = Wrel_flat[k*128+h]   ([R,128,128] is contiguous [256,128])
//   B[256+d, h]   = Wroot[d*128+h]
// Tile: 64 rows x 128 cols x BK=16, 256 threads, 8x4 outputs/thread.
// ---------------------------------------------------------------------------
__global__ void __launch_bounds__(256, 2)
gemm_kernel(const float* __restrict__ Wrel, const float* __restrict__ Wroot,
            const float* __restrict__ bias, const float* __restrict__ res,
            float* __restrict__ out) {
    __shared__ float As[16 * 68];   // [k][row], padded stride 68
    __shared__ float Bs[16 * 128];  // [k][h]

    const int tid = threadIdx.x;
    const int rowBase = blockIdx.x * 64;

    // A loader: each thread owns one row (tid/4) and a float4 of k (tid&3)
    const int arow = tid >> 2;
    const int akq = tid & 3;
    const int grow = rowBase + arow;
    const bool rowok = grow < NN;
    float ic0 = 0.f, ic1 = 0.f;
    if (rowok) {
        const float c0 = g_cnt[(size_t)grow * 2 + 0];
        const float c1 = g_cnt[(size_t)grow * 2 + 1];
        ic0 = 1.0f / fmaxf(c0, 1.0f);
        ic1 = 1.0f / fmaxf(c1, 1.0f);
    }
    const float4* sums4 = (const float4*)(g_sums + (size_t)grow * (NR * NF));
    const float4* hn4 = (const float4*)(g_hn + (size_t)grow * NF);

    // B loader: rows bk, bk+8; cols bh..bh+3
    const int bk = tid >> 5;
    const int bh = (tid & 31) * 4;

    // compute mapping: warp ty owns rows ty*8..+7; lane tx owns cols tx*4..+3
    const int ty = tid >> 5;
    const int tx = tid & 31;

    float acc[8][4];
#pragma unroll
    for (int i = 0; i < 8; i++)
#pragma unroll
        for (int j = 0; j < 4; j++) acc[i][j] = 0.f;

#pragma unroll 1
    for (int kt = 0; kt < 24; kt++) {
        // stage global loads into registers
        float4 a = make_float4(0.f, 0.f, 0.f, 0.f);
        if (rowok) {
            if (kt < 16) {
                a = sums4[kt * 4 + akq];
                const float ic = (kt < 8) ? ic0 : ic1;
                a.x *= ic; a.y *= ic; a.z *= ic; a.w *= ic;
            } else {
                a = hn4[(kt - 16) * 4 + akq];
            }
        }
        const float* Bg = (kt < 16) ? (Wrel + kt * (16 * NF))
                                    : (Wroot + (kt - 16) * (16 * NF));
        const float4 b0 = *(const float4*)(Bg + bk * NF + bh);
        const float4 b1 = *(const float4*)(Bg + (bk + 8) * NF + bh);

        __syncthreads();  // previous tile compute done before overwrite
        As[(akq * 4 + 0) * 68 + arow] = a.x;
        As[(akq * 4 + 1) * 68 + arow] = a.y;
        As[(akq * 4 + 2) * 68 + arow] = a.z;
        As[(akq * 4 + 3) * 68 + arow] = a.w;
        *(float4*)(Bs + bk * NF + bh) = b0;
        *(float4*)(Bs + (bk + 8) * NF + bh) = b1;
        __syncthreads();

#pragma unroll
        for (int kk = 0; kk < 16; kk++) {
            const float4 a0 = *(const float4*)(As + kk * 68 + ty * 8);
            const float4 a1 = *(const float4*)(As + kk * 68 + ty * 8 + 4);
            const float4 b = *(const float4*)(Bs + kk * NF + tx * 4);
            const float ra[8] = {a0.x, a0.y, a0.z, a0.w, a1.x, a1.y, a1.z, a1.w};
            const float rb[4] = {b.x, b.y, b.z, b.w};
#pragma unroll
            for (int i = 0; i < 8; i++)
#pragma unroll
                for (int j = 0; j < 4; j++) acc[i][j] += ra[i] * rb[j];
        }
    }

    // epilogue: + bias, relu, + residual, store
    const float4 bv = *(const float4*)(bias + tx * 4);
#pragma unroll
    for (int i = 0; i < 8; i++) {
        const int gr = rowBase + ty * 8 + i;
        if (gr < NN) {
            float4 o;
            o.x = fmaxf(acc[i][0] + bv.x, 0.f);
            o.y = fmaxf(acc[i][1] + bv.y, 0.f);
            o.z = fmaxf(acc[i][2] + bv.z, 0.f);
            o.w = fmaxf(acc[i][3] + bv.w, 0.f);
            if (res) {
                const float4 rv = *(const float4*)(res + (size_t)gr * NF + tx * 4);
                o.x += rv.x; o.y += rv.y; o.z += rv.z; o.w += rv.w;
            }
            *(float4*)(out + (size_t)gr * NF + tx * 4) = o;
        }
    }
}

// ---------------------------------------------------------------------------
extern "C" void kernel_launch(void* const* d_in, const int* in_sizes, int n_in,
                              void* d_out, int out_size) {
    const float* x = (const float*)d_in[0];
    const int* ei = (const int*)d_in[1];
    const int* et = (const int*)d_in[2];
    const float* W0rel = (const float*)d_in[3];
    const float* W0root = (const float*)d_in[4];
    const float* b0 = (const float*)d_in[5];
    const float* Wsrel = (const float*)d_in[6];
    const float* Wsroot = (const float*)d_in[7];
    const float* bs = (const float*)d_in[8];
    float* outp = (float*)d_out;

    const int* src = ei;
    const int* dst = ei + NE;

    void *p_sums = 0, *p_cnt = 0, *p_stats = 0, *p_h = 0;
    cudaGetSymbolAddress(&p_sums, g_sums);
    cudaGetSymbolAddress(&p_cnt, g_cnt);
    cudaGetSymbolAddress(&p_stats, g_stats);
    cudaGetSymbolAddress(&p_h, g_h);

    for (int c = 0; c < 4; c++) {
        const float* in = (c == 0) ? x : (const float*)p_h;
        const float* Wrel = (c == 0) ? W0rel : Wsrel + (size_t)(c - 1) * NR * NF * NF;
        const float* Wroot = (c == 0) ? W0root : Wsroot + (size_t)(c - 1) * NF * NF;
        const float* bb = (c == 0) ? b0 : bs + (c - 1) * NF;
        const float* res = (c == 0) ? (const float*)0 : (const float*)p_h;
        float* o = (c == 3) ? outp : (float*)p_h;

        cudaMemsetAsync(p_stats, 0, 2 * NF * sizeof(float));
        stats_kernel<<<256, 256>>>(in);
        bn_kernel<<<(NN * NF / 4) / 256 + 1, 256>>>(in);

        cudaMemsetAsync(p_sums, 0, (size_t)NN * NR * NF * sizeof(float));
        cudaMemsetAsync(p_cnt, 0, (size_t)NN * NR * sizeof(float));
        scatter_kernel<<<NE / 8, 256>>>(src, dst, et);

        gemm_kernel<<<(NN + 63) / 64, 256>>>(Wrel, Wroot, bb, res, o);
    }
}

// round 2
// speedup vs baseline: 1.6855x; 1.6855x over previous
#include <cuda_runtime.h>

#define NN 50000
#define NF 128
#define NE 600000
#define NR 2
#define NSEG (NN * NR)          // 100000
#define SCAN_BLKS 98            // ceil(NSEG / 1024)

// scratch (device globals: no allocation allowed)
__device__ float g_h[(size_t)NN * NF];
__device__ float g_hn[(size_t)NN * NF];
__device__ float g_mean[(size_t)NSEG * NF];
__device__ float g_stats[2 * NF];
__device__ int   g_deg[NSEG];
__device__ int   g_cursor[NSEG];
__device__ float g_icnt[NSEG];
__device__ int   g_csr[NE];
__device__ int   g_bsum[128];

// ---------------------------------------------------------------------------
// CSR build (once per launch)
// ---------------------------------------------------------------------------
__global__ void hist_kernel(const int* __restrict__ dst,
                            const int* __restrict__ et) {
    const int e = blockIdx.x * blockDim.x + threadIdx.x;
    if (e >= NE) return;
    atomicAdd(&g_deg[dst[e] * NR + et[e]], 1);
}

// block-level exclusive scan: 98 blocks x 256 threads, 4 segments/thread
__global__ void scan1_kernel() {
    __shared__ int sh[256];
    const int t = threadIdx.x;
    const int base = blockIdx.x * 1024 + t * 4;
    int v[4];
#pragma unroll
    for (int k = 0; k < 4; k++)
        v[k] = (base + k < NSEG) ? g_deg[base + k] : 0;
    int sum = v[0] + v[1] + v[2] + v[3];
    sh[t] = sum;
    __syncthreads();
#pragma unroll
    for (int off = 1; off < 256; off <<= 1) {
        int add = (t >= off) ? sh[t - off] : 0;
        __syncthreads();
        sh[t] += add;
        __syncthreads();
    }
    int ex = sh[t] - sum;
#pragma unroll
    for (int k = 0; k < 4; k++) {
        if (base + k < NSEG) g_cursor[base + k] = ex;
        ex += v[k];
    }
    if (t == 255) g_bsum[blockIdx.x] = sh[255];
}

__global__ void scan2_kernel() {
    if (threadIdx.x == 0) {
        int a = 0;
        for (int i = 0; i < SCAN_BLKS; i++) {
            int v = g_bsum[i];
            g_bsum[i] = a;
            a += v;
        }
    }
}

__global__ void addoff_kernel() {
    const int i = blockIdx.x * blockDim.x + threadIdx.x;
    if (i >= NSEG) return;
    g_cursor[i] += g_bsum[i >> 10];
    g_icnt[i] = 1.0f / (float)max(g_deg[i], 1);
}

__global__ void fill_kernel(const int* __restrict__ src,
                            const int* __restrict__ dst,
                            const int* __restrict__ et) {
    const int e = blockIdx.x * blockDim.x + threadIdx.x;
    if (e >= NE) return;
    const int pos = atomicAdd(&g_cursor[dst[e] * NR + et[e]], 1);
    g_csr[pos] = src[e];
}

// ---------------------------------------------------------------------------
// Column stats: sum and sumsq per feature (for BatchNorm)
// ---------------------------------------------------------------------------
__global__ void stats_kernel(const float* __restrict__ in) {
    __shared__ float ss[256], sq[256];
    const int tid = threadIdx.x;
    const int f = tid & 127;
    const int half = tid >> 7;
    float s = 0.f, s2 = 0.f;
    for (int r = blockIdx.x * 2 + half; r < NN; r += gridDim.x * 2) {
        float v = in[r * NF + f];
        s += v;
        s2 += v * v;
    }
    ss[tid] = s;
    sq[tid] = s2;
    __syncthreads();
    if (tid < 128) {
        atomicAdd(&g_stats[f], ss[tid] + ss[tid + 128]);
        atomicAdd(&g_stats[NF + f], sq[tid] + sq[tid + 128]);
    }
}

// ---------------------------------------------------------------------------
// BatchNorm normalize: g_hn = (in - mu) * rsqrt(var + eps) + 1e-4
// ---------------------------------------------------------------------------
__global__ void bn_kernel(const float* __restrict__ in) {
    const int i = blockIdx.x * blockDim.x + threadIdx.x;
    const int total = NN * NF / 4;
    if (i >= total) return;
    const int fb = (i * 4) & 127;
    const float4 v = ((const float4*)in)[i];
    const float invn = 1.0f / NN;
    float4 o;
    float mu, var, rs;
    mu = g_stats[fb + 0] * invn; var = g_stats[NF + fb + 0] * invn - mu * mu;
    rs = rsqrtf(var + 1e-5f); o.x = (v.x - mu) * rs + 1e-4f;
    mu = g_stats[fb + 1] * invn; var = g_stats[NF + fb + 1] * invn - mu * mu;
    rs = rsqrtf(var + 1e-5f); o.y = (v.y - mu) * rs + 1e-4f;
    mu = g_stats[fb + 2] * invn; var = g_stats[NF + fb + 2] * invn - mu * mu;
    rs = rsqrtf(var + 1e-5f); o.z = (v.z - mu) * rs + 1e-4f;
    mu = g_stats[fb + 3] * invn; var = g_stats[NF + fb + 3] * invn - mu * mu;
    rs = rsqrtf(var + 1e-5f); o.w = (v.w - mu) * rs + 1e-4f;
    ((float4*)g_hn)[i] = o;
}

// ---------------------------------------------------------------------------
// Gather aggregation: one warp per (node, relation) segment.
// Reads its edge list from g_csr, accumulates hn[src] in registers,
// writes mean (sum * icnt) to g_mean. No atomics, no memset.
// ---------------------------------------------------------------------------
__global__ void agg_kernel() {
    const int seg = (blockIdx.x * blockDim.x + threadIdx.x) >> 5;
    const int lane = threadIdx.x & 31;
    if (seg >= NSEG) return;
    const int end = g_cursor[seg];          // cursor == offset + deg after fill
    const int deg = g_deg[seg];
    const int start = end - deg;
    float4 acc = make_float4(0.f, 0.f, 0.f, 0.f);
    const float4* hn4 = (const float4*)g_hn;
    for (int e = start; e < end; e++) {
        const int s = __ldg(&g_csr[e]);
        const float4 v = hn4[(size_t)s * 32 + lane];
        acc.x += v.x; acc.y += v.y; acc.z += v.z; acc.w += v.w;
    }
    const float ic = g_icnt[seg];
    acc.x *= ic; acc.y *= ic; acc.z *= ic; acc.w *= ic;
    ((float4*)g_mean)[(size_t)seg * 32 + lane] = acc;
}

// ---------------------------------------------------------------------------
// Fused GEMM: out[n,h] = relu( sum_k A[n,k] * B[k,h] + bias[h] ) (+ res[n,h])
//   A[n, k<256] = g_mean[n,k]   (per-relation mean, already divided)
//   A[n, 256+d] = g_hn[n,d]     (root term)
// Tile: 64 rows x 128 cols x BK=16, 256 threads, 8x4 outputs/thread.
// ---------------------------------------------------------------------------
__global__ void __launch_bounds__(256, 2)
gemm_kernel(const float* __restrict__ Wrel, const float* __restrict__ Wroot,
            const float* __restrict__ bias, const float* __restrict__ res,
            float* __restrict__ out) {
    __shared__ float As[16 * 68];   // [k][row], padded stride 68
    __shared__ float Bs[16 * 128];  // [k][h]

    const int tid = threadIdx.x;
    const int rowBase = blockIdx.x * 64;

    const int arow = tid >> 2;
    const int akq = tid & 3;
    const int grow = rowBase + arow;
    const bool rowok = grow < NN;

    const float4* mean4 = (const float4*)(g_mean + (size_t)grow * (NR * NF));
    const float4* hn4 = (const float4*)(g_hn + (size_t)grow * NF);

    const int bk = tid >> 5;
    const int bh = (tid & 31) * 4;
    const int ty = tid >> 5;
    const int tx = tid & 31;

    float acc[8][4];
#pragma unroll
    for (int i = 0; i < 8; i++)
#pragma unroll
        for (int j = 0; j < 4; j++) acc[i][j] = 0.f;

#pragma unroll 1
    for (int kt = 0; kt < 24; kt++) {
        float4 a = make_float4(0.f, 0.f, 0.f, 0.f);
        if (rowok)
            a = (kt < 16) ? mean4[kt * 4 + akq] : hn4[(kt - 16) * 4 + akq];
        const float* Bg = (kt < 16) ? (Wrel + kt * (16 * NF))
                                    : (Wroot + (kt - 16) * (16 * NF));
        const float4 b0 = *(const float4*)(Bg + bk * NF + bh);
        const float4 b1 = *(const float4*)(Bg + (bk + 8) * NF + bh);

        __syncthreads();
        As[(akq * 4 + 0) * 68 + arow] = a.x;
        As[(akq * 4 + 1) * 68 + arow] = a.y;
        As[(akq * 4 + 2) * 68 + arow] = a.z;
        As[(akq * 4 + 3) * 68 + arow] = a.w;
        *(float4*)(Bs + bk * NF + bh) = b0;
        *(float4*)(Bs + (bk + 8) * NF + bh) = b1;
        __syncthreads();

#pragma unroll
        for (int kk = 0; kk < 16; kk++) {
            const float4 a0 = *(const float4*)(As + kk * 68 + ty * 8);
            const float4 a1 = *(const float4*)(As + kk * 68 + ty * 8 + 4);
            const float4 b = *(const float4*)(Bs + kk * NF + tx * 4);
            const float ra[8] = {a0.x, a0.y, a0.z, a0.w, a1.x, a1.y, a1.z, a1.w};
            const float rb[4] = {b.x, b.y, b.z, b.w};
#pragma unroll
            for (int i = 0; i < 8; i++)
#pragma unroll
                for (int j = 0; j < 4; j++) acc[i][j] += ra[i] * rb[j];
        }
    }

    const float4 bv = *(const float4*)(bias + tx * 4);
#pragma unroll
    for (int i = 0; i < 8; i++) {
        const int gr = rowBase + ty * 8 + i;
        if (gr < NN) {
            float4 o;
            o.x = fmaxf(acc[i][0] + bv.x, 0.f);
            o.y = fmaxf(acc[i][1] + bv.y, 0.f);
            o.z = fmaxf(acc[i][2] + bv.z, 0.f);
            o.w = fmaxf(acc[i][3] + bv.w, 0.f);
            if (res) {
                const float4 rv = *(const float4*)(res + (size_t)gr * NF + tx * 4);
                o.x += rv.x; o.y += rv.y; o.z += rv.z; o.w += rv.w;
            }
            *(float4*)(out + (size_t)gr * NF + tx * 4) = o;
        }
    }
}

// ---------------------------------------------------------------------------
extern "C" void kernel_launch(void* const* d_in, const int* in_sizes, int n_in,
                              void* d_out, int out_size) {
    const float* x = (const float*)d_in[0];
    const int* ei = (const int*)d_in[1];
    const int* et = (const int*)d_in[2];
    const float* W0rel = (const float*)d_in[3];
    const float* W0root = (const float*)d_in[4];
    const float* b0 = (const float*)d_in[5];
    const float* Wsrel = (const float*)d_in[6];
    const float* Wsroot = (const float*)d_in[7];
    const float* bs = (const float*)d_in[8];
    float* outp = (float*)d_out;

    const int* src = ei;
    const int* dst = ei + NE;

    void *p_stats = 0, *p_h = 0, *p_deg = 0;
    cudaGetSymbolAddress(&p_stats, g_stats);
    cudaGetSymbolAddress(&p_h, g_h);
    cudaGetSymbolAddress(&p_deg, g_deg);

    // ---- CSR build (once per launch) ----
    cudaMemsetAsync(p_deg, 0, NSEG * sizeof(int));
    hist_kernel<<<(NE + 255) / 256, 256>>>(dst, et);
    scan1_kernel<<<SCAN_BLKS, 256>>>();
    scan2_kernel<<<1, 32>>>();
    addoff_kernel<<<(NSEG + 255) / 256, 256>>>();
    fill_kernel<<<(NE + 255) / 256, 256>>>(src, dst, et);

    // ---- layers ----
    for (int c = 0; c < 4; c++) {
        const float* in = (c == 0) ? x : (const float*)p_h;
        const float* Wrel = (c == 0) ? W0rel : Wsrel + (size_t)(c - 1) * NR * NF * NF;
        const float* Wroot = (c == 0) ? W0root : Wsroot + (size_t)(c - 1) * NF * NF;
        const float* bb = (c == 0) ? b0 : bs + (c - 1) * NF;
        const float* res = (c == 0) ? (const float*)0 : (const float*)p_h;
        float* o = (c == 3) ? outp : (float*)p_h;

        cudaMemsetAsync(p_stats, 0, 2 * NF * sizeof(float));
        stats_kernel<<<256, 256>>>(in);
        bn_kernel<<<(NN * NF / 4 + 255) / 256, 256>>>(in);

        agg_kernel<<<(NSEG * 32 + 255) / 256, 256>>>();

        gemm_kernel<<<(NN + 63) / 64, 256>>>(Wrel, Wroot, bb, res, o);
    }
}

// round 4
// speedup vs baseline: 2.2548x; 1.3378x over previous
#include <cuda_runtime.h>
#include <cuda_bf16.h>
#include <cstdint>

#define NN 50000
#define NF 128
#define NE 600000
#define NR 2
#define NSEG (NN * NR)          // 100000
#define SCAN_BLKS 98            // ceil(NSEG / 1024)
#define KP 1152                 // K' = 3 * 384 (split-precision concat)
#define KCH 64                  // K chunk
#define NCH 18                  // 1152 / 64

// ---------------- scratch (device globals; no allocation allowed) ----------
__device__ float g_h[(size_t)NN * NF];
__device__ float g_hn[(size_t)NN * NF];
__device__ float g_stats[2 * NF];
__device__ int   g_deg[NSEG];
__device__ int   g_cursor[NSEG];
__device__ float g_icnt[NSEG];
__device__ int   g_csr[NE];
__device__ int   g_bsum[128];
// bf16 split operands
__device__ unsigned short g_hhi[(size_t)NN * NF];
__device__ unsigned short g_hlo[(size_t)NN * NF];
__device__ unsigned short g_mhi[(size_t)NN * NR * NF];
__device__ unsigned short g_mlo[(size_t)NN * NR * NF];
__device__ unsigned short g_wb[(size_t)4 * NF * KP];   // [layer][n=128][k'=1152]

// ---------------- helpers ---------------------------------------------------
__device__ __forceinline__ uint32_t smem_u32(const void* p) {
    uint32_t a;
    asm("{ .reg .u64 t; cvta.to.shared.u64 t, %1; cvt.u32.u64 %0, t; }"
        : "=r"(a) : "l"(p));
    return a;
}
#define SWZ128(off) ((off) ^ (((off) >> 3) & 0x70))
#define CP_ASYNC16(sm, gp) \
    asm volatile("cp.async.cg.shared.global [%0], [%1], 16;" :: "r"(sm), "l"(gp) : "memory")
#define CP_COMMIT() asm volatile("cp.async.commit_group;" ::: "memory")
#define CP_WAIT0()  asm volatile("cp.async.wait_group 0;" ::: "memory")

static __device__ __forceinline__ unsigned short bfu(float f) {
    __nv_bfloat16 b = __float2bfloat16(f);
    return *(unsigned short*)&b;
}
static __device__ __forceinline__ float bff(unsigned short u) {
    __nv_bfloat16 b = *(__nv_bfloat16*)&u;
    return __bfloat162float(b);
}
static __device__ __forceinline__ void split4(float4 v, uint2& hi, uint2& lo) {
    unsigned short hx = bfu(v.x), hy = bfu(v.y), hz = bfu(v.z), hw = bfu(v.w);
    unsigned short lx = bfu(v.x - bff(hx)), ly = bfu(v.y - bff(hy));
    unsigned short lz = bfu(v.z - bff(hz)), lw = bfu(v.w - bff(hw));
    hi.x = (uint32_t)hx | ((uint32_t)hy << 16);
    hi.y = (uint32_t)hz | ((uint32_t)hw << 16);
    lo.x = (uint32_t)lx | ((uint32_t)ly << 16);
    lo.y = (uint32_t)lz | ((uint32_t)lw << 16);
}

// ---------------------------------------------------------------------------
// CSR build (once per launch)
// ---------------------------------------------------------------------------
__global__ void hist_kernel(const int* __restrict__ dst, const int* __restrict__ et) {
    const int e = blockIdx.x * blockDim.x + threadIdx.x;
    if (e >= NE) return;
    atomicAdd(&g_deg[dst[e] * NR + et[e]], 1);
}
__global__ void scan1_kernel() {
    __shared__ int sh[256];
    const int t = threadIdx.x;
    const int base = blockIdx.x * 1024 + t * 4;
    int v[4];
#pragma unroll
    for (int k = 0; k < 4; k++) v[k] = (base + k < NSEG) ? g_deg[base + k] : 0;
    int sum = v[0] + v[1] + v[2] + v[3];
    sh[t] = sum;
    __syncthreads();
#pragma unroll
    for (int off = 1; off < 256; off <<= 1) {
        int add = (t >= off) ? sh[t - off] : 0;
        __syncthreads();
        sh[t] += add;
        __syncthreads();
    }
    int ex = sh[t] - sum;
#pragma unroll
    for (int k = 0; k < 4; k++) {
        if (base + k < NSEG) g_cursor[base + k] = ex;
        ex += v[k];
    }
    if (t == 255) g_bsum[blockIdx.x] = sh[255];
}
__global__ void scan2_kernel() {
    if (threadIdx.x == 0) {
        int a = 0;
        for (int i = 0; i < SCAN_BLKS; i++) { int v = g_bsum[i]; g_bsum[i] = a; a += v; }
    }
}
__global__ void addoff_kernel() {
    const int i = blockIdx.x * blockDim.x + threadIdx.x;
    if (i >= NSEG) return;
    g_cursor[i] += g_bsum[i >> 10];
    g_icnt[i] = 1.0f / (float)max(g_deg[i], 1);
}
__global__ void fill_kernel(const int* __restrict__ src, const int* __restrict__ dst,
                            const int* __restrict__ et) {
    const int e = blockIdx.x * blockDim.x + threadIdx.x;
    if (e >= NE) return;
    const int pos = atomicAdd(&g_cursor[dst[e] * NR + et[e]], 1);
    g_csr[pos] = src[e];
}

// ---------------------------------------------------------------------------
// Weight prep: g_wb[l][n][k'] for k'<384: hi(W(k,n)); 384..767: hi; 768+: lo
//   W(k,n): k<256 -> Wrel[k*128+n], else Wroot[(k-256)*128+n]
// ---------------------------------------------------------------------------
__global__ void wt_kernel(const float* __restrict__ Wrel, const float* __restrict__ Wroot,
                          int layer) {
    const int i = blockIdx.x * blockDim.x + threadIdx.x;   // n*1152 + k'
    if (i >= NF * KP) return;
    const int n = i / KP;
    const int kp = i % KP;
    const int k = (kp < 384) ? kp : (kp < 768) ? (kp - 384) : (kp - 768);
    const float w = (k < 256) ? Wrel[k * NF + n] : Wroot[(k - 256) * NF + n];
    const unsigned short hi = bfu(w);
    g_wb[(size_t)layer * NF * KP + i] = (kp < 768) ? hi : bfu(w - bff(hi));
}

// ---------------------------------------------------------------------------
// Column stats (BatchNorm)
// ---------------------------------------------------------------------------
__global__ void stats_kernel(const float* __restrict__ in) {
    __shared__ float ss[256], sq[256];
    const int tid = threadIdx.x;
    const int f = tid & 127;
    const int half = tid >> 7;
    float s = 0.f, s2 = 0.f;
    for (int r = blockIdx.x * 2 + half; r < NN; r += gridDim.x * 2) {
        float v = in[r * NF + f];
        s += v; s2 += v * v;
    }
    ss[tid] = s; sq[tid] = s2;
    __syncthreads();
    if (tid < 128) {
        atomicAdd(&g_stats[f], ss[tid] + ss[tid + 128]);
        atomicAdd(&g_stats[NF + f], sq[tid] + sq[tid + 128]);
    }
}

// ---------------------------------------------------------------------------
// BN normalize: fp32 g_hn (for agg) + bf16 hi/lo (root part of GEMM A)
// ---------------------------------------------------------------------------
__global__ void bn_kernel(const float* __restrict__ in) {
    const int i = blockIdx.x * blockDim.x + threadIdx.x;
    const int total = NN * NF / 4;
    if (i >= total) return;
    const int fb = (i * 4) & 127;
    const float4 v = ((const float4*)in)[i];
    const float invn = 1.0f / NN;
    float4 o;
    float mu, var, rs;
    mu = g_stats[fb + 0] * invn; var = g_stats[NF + fb + 0] * invn - mu * mu;
    rs = rsqrtf(var + 1e-5f); o.x = (v.x - mu) * rs + 1e-4f;
    mu = g_stats[fb + 1] * invn; var = g_stats[NF + fb + 1] * invn - mu * mu;
    rs = rsqrtf(var + 1e-5f); o.y = (v.y - mu) * rs + 1e-4f;
    mu = g_stats[fb + 2] * invn; var = g_stats[NF + fb + 2] * invn - mu * mu;
    rs = rsqrtf(var + 1e-5f); o.z = (v.z - mu) * rs + 1e-4f;
    mu = g_stats[fb + 3] * invn; var = g_stats[NF + fb + 3] * invn - mu * mu;
    rs = rsqrtf(var + 1e-5f); o.w = (v.w - mu) * rs + 1e-4f;
    ((float4*)g_hn)[i] = o;
    uint2 hi, lo;
    split4(o, hi, lo);
    ((uint2*)g_hhi)[i] = hi;
    ((uint2*)g_hlo)[i] = lo;
}

// ---------------------------------------------------------------------------
// Gather aggregation: warp per (node, relation) segment -> bf16 hi/lo mean
// ---------------------------------------------------------------------------
__global__ void agg_kernel() {
    const int seg = (blockIdx.x * blockDim.x + threadIdx.x) >> 5;
    const int lane = threadIdx.x & 31;
    if (seg >= NSEG) return;
    const int end = g_cursor[seg];
    const int deg = g_deg[seg];
    const int start = end - deg;
    float4 acc = make_float4(0.f, 0.f, 0.f, 0.f);
    const float4* hn4 = (const float4*)g_hn;
    for (int e = start; e < end; e++) {
        const int s = __ldg(&g_csr[e]);
        const float4 v = hn4[(size_t)s * 32 + lane];
        acc.x += v.x; acc.y += v.y; acc.z += v.z; acc.w += v.w;
    }
    const float ic = g_icnt[seg];
    acc.x *= ic; acc.y *= ic; acc.z *= ic; acc.w *= ic;
    uint2 hi, lo;
    split4(acc, hi, lo);
    ((uint2*)g_mhi)[(size_t)seg * 32 + lane] = hi;
    ((uint2*)g_mlo)[(size_t)seg * 32 + lane] = lo;
}

// ---------------------------------------------------------------------------
// HMMA GEMM (mma.sync m16n8k16 bf16): out[128blk x 128] = A'[.,1152] B'^T
// A' chunks 0-5 = hi, 6-11 = lo, 12-17 = hi; within 6: kc<4 mean, else root.
// 8 warps (2M x 4N), warp tile 64x32, cp.async double-buffered K=64 chunks.
// Epilogue: +bias, relu, +residual.
// ---------------------------------------------------------------------------
#define TILEB 16384                          // 128 rows x 128 bytes
#define BUFB  (2 * TILEB)                    // A + B
#define SMEMB (2 * BUFB + 1024)

__global__ void __launch_bounds__(256)
gemm_mma(const unsigned short* __restrict__ Wb, const float* __restrict__ bias,
         const float* __restrict__ res, float* __restrict__ out) {
    extern __shared__ char smraw[];
    uint32_t sb0 = smem_u32(smraw);
    const uint32_t sb = (sb0 + 1023u) & ~1023u;

    const int tid = threadIdx.x;
    const int wid = tid >> 5;
    const int lane = tid & 31;
    const int rowBase = blockIdx.x * 128;

    // loader mapping: row r (two threads per row), 4 x 16B pieces each
    const int r = tid >> 1;
    const int jb = (tid & 1) * 4;
    const int gnode = min(rowBase + r, NN - 1);
    const unsigned short* brow = Wb + (size_t)r * KP;

    // compute mapping
    const int warpM = wid >> 2;          // 0..1 -> 64 rows
    const int warpN = wid & 3;           // 0..3 -> 32 cols

    float acc[4][4][4];
#pragma unroll
    for (int mi = 0; mi < 4; mi++)
#pragma unroll
        for (int ni = 0; ni < 4; ni++)
#pragma unroll
            for (int q = 0; q < 4; q++) acc[mi][ni][q] = 0.f;

    // ldmatrix lane addressing (byte offsets within 16KB tile, pre-swizzle)
    const int a_row = warpM * 64 + ((lane >> 3) & 1) * 8 + (lane & 7);
    const int a_k8 = (lane >> 4) * 8;
    const int b_row = warpN * 32 + (lane & 7);
    const int b_k8 = ((lane >> 3) & 1) * 8;

    // ---- loader lambda (macro-style) ----
#define LOAD_CHUNK(c, buf) do { \
        const uint32_t aB = sb + (buf) * BUFB; \
        const uint32_t bB = aB + TILEB; \
        const int part = ((c) >= 6 && (c) < 12) ? 1 : 0; \
        const int kc = (c) % 6; \
        const unsigned short* arow = (kc < 4) \
            ? (part ? g_mlo : g_mhi) + (size_t)gnode * 256 + kc * 64 \
            : (part ? g_hlo : g_hhi) + (size_t)gnode * 128 + (kc - 4) * 64; \
        const unsigned short* bsrc = brow + (c) * 64; \
        _Pragma("unroll") \
        for (int i = 0; i < 4; i++) { \
            const int j = jb + i; \
            const uint32_t sw = SWZ128(r * 128 + j * 16); \
            CP_ASYNC16(aB + sw, arow + j * 8); \
            CP_ASYNC16(bB + sw, bsrc + j * 8); \
        } \
        CP_COMMIT(); \
    } while (0)

    LOAD_CHUNK(0, 0);

#pragma unroll 1
    for (int c = 0; c < NCH; c++) {
        CP_WAIT0();
        __syncthreads();
        if (c + 1 < NCH) LOAD_CHUNK(c + 1, (c + 1) & 1);

        const uint32_t aB = sb + (c & 1) * BUFB;
        const uint32_t bB = aB + TILEB;
#pragma unroll
        for (int k16 = 0; k16 < 4; k16++) {
            uint32_t afr[4][4], bfr[4][2];
#pragma unroll
            for (int mi = 0; mi < 4; mi++) {
                const uint32_t addr = aB +
                    SWZ128((a_row + mi * 16) * 128 + (k16 * 16 + a_k8) * 2);
                asm volatile("ldmatrix.sync.aligned.m8n8.x4.shared.b16 "
                             "{%0,%1,%2,%3}, [%4];"
                             : "=r"(afr[mi][0]), "=r"(afr[mi][1]),
                               "=r"(afr[mi][2]), "=r"(afr[mi][3])
                             : "r"(addr));
            }
#pragma unroll
            for (int ni = 0; ni < 4; ni++) {
                const uint32_t addr = bB +
                    SWZ128((b_row + ni * 8) * 128 + (k16 * 16 + b_k8) * 2);
                asm volatile("ldmatrix.sync.aligned.m8n8.x2.shared.b16 "
                             "{%0,%1}, [%2];"
                             : "=r"(bfr[ni][0]), "=r"(bfr[ni][1])
                             : "r"(addr));
            }
#pragma unroll
            for (int mi = 0; mi < 4; mi++)
#pragma unroll
                for (int ni = 0; ni < 4; ni++) {
                    asm volatile(
                        "mma.sync.aligned.m16n8k16.row.col.f32.bf16.bf16.f32 "
                        "{%0,%1,%2,%3}, {%4,%5,%6,%7}, {%8,%9}, {%0,%1,%2,%3};"
                        : "+f"(acc[mi][ni][0]), "+f"(acc[mi][ni][1]),
                          "+f"(acc[mi][ni][2]), "+f"(acc[mi][ni][3])
                        : "r"(afr[mi][0]), "r"(afr[mi][1]),
                          "r"(afr[mi][2]), "r"(afr[mi][3]),
                          "r"(bfr[ni][0]), "r"(bfr[ni][1]));
                }
        }
    }
#undef LOAD_CHUNK

    // ---- epilogue: +bias, relu, +residual ----
    const int mBase = rowBase + warpM * 64 + (lane >> 2);
    const int nBase = warpN * 32 + (lane & 3) * 2;
#pragma unroll
    for (int ni = 0; ni < 4; ni++) {
        const int n0 = nBase + ni * 8;
        const float2 bv = *(const float2*)(bias + n0);
#pragma unroll
        for (int mi = 0; mi < 4; mi++) {
#pragma unroll
            for (int h = 0; h < 2; h++) {
                const int m = mBase + mi * 16 + h * 8;
                if (m < NN) {
                    float2 o;
                    o.x = fmaxf(acc[mi][ni][h * 2 + 0] + bv.x, 0.f);
                    o.y = fmaxf(acc[mi][ni][h * 2 + 1] + bv.y, 0.f);
                    if (res) {
                        const float2 rv = *(const float2*)(res + (size_t)m * NF + n0);
                        o.x += rv.x; o.y += rv.y;
                    }
                    *(float2*)(out + (size_t)m * NF + n0) = o;
                }
            }
        }
    }
}

// ---------------------------------------------------------------------------
extern "C" void kernel_launch(void* const* d_in, const int* in_sizes, int n_in,
                              void* d_out, int out_size) {
    const float* x = (const float*)d_in[0];
    const int* ei = (const int*)d_in[1];
    const int* et = (const int*)d_in[2];
    const float* W0rel = (const float*)d_in[3];
    const float* W0root = (const float*)d_in[4];
    const float* b0 = (const float*)d_in[5];
    const float* Wsrel = (const float*)d_in[6];
    const float* Wsroot = (const float*)d_in[7];
    const float* bs = (const float*)d_in[8];
    float* outp = (float*)d_out;

    const int* src = ei;
    const int* dst = ei + NE;

    void *p_stats = 0, *p_h = 0, *p_deg = 0, *p_wb = 0;
    cudaGetSymbolAddress(&p_stats, g_stats);
    cudaGetSymbolAddress(&p_h, g_h);
    cudaGetSymbolAddress(&p_deg, g_deg);
    cudaGetSymbolAddress(&p_wb, g_wb);

    static int smem_set = 0;
    if (!smem_set) {
        cudaFuncSetAttribute(gemm_mma, cudaFuncAttributeMaxDynamicSharedMemorySize, SMEMB);
        smem_set = 1;
    }

    // ---- CSR build + weight prep (once per launch) ----
    cudaMemsetAsync(p_deg, 0, NSEG * sizeof(int));
    hist_kernel<<<(NE + 255) / 256, 256>>>(dst, et);
    scan1_kernel<<<SCAN_BLKS, 256>>>();
    scan2_kernel<<<1, 32>>>();
    addoff_kernel<<<(NSEG + 255) / 256, 256>>>();
    fill_kernel<<<(NE + 255) / 256, 256>>>(src, dst, et);
    for (int l = 0; l < 4; l++) {
        const float* Wrel = (l == 0) ? W0rel : Wsrel + (size_t)(l - 1) * NR * NF * NF;
        const float* Wroot = (l == 0) ? W0root : Wsroot + (size_t)(l - 1) * NF * NF;
        wt_kernel<<<(NF * KP + 255) / 256, 256>>>(Wrel, Wroot, l);
    }

    // ---- layers ----
    for (int c = 0; c < 4; c++) {
        const float* in = (c == 0) ? x : (const float*)p_h;
        const float* bb = (c == 0) ? b0 : bs + (c - 1) * NF;
        const float* res = (c == 0) ? (const float*)0 : (const float*)p_h;
        float* o = (c == 3) ? outp : (float*)p_h;
        const unsigned short* wb = (const unsigned short*)p_wb + (size_t)c * NF * KP;

        cudaMemsetAsync(p_stats, 0, 2 * NF * sizeof(float));
        stats_kernel<<<256, 256>>>(in);
        bn_kernel<<<(NN * NF / 4 + 255) / 256, 256>>>(in);
        agg_kernel<<<(NSEG * 32 + 255) / 256, 256>>>();
        gemm_mma<<<(NN + 127) / 128, 256, SMEMB>>>(wb, bb, res, o);
    }
}

// round 5
// speedup vs baseline: 2.4681x; 1.0946x over previous
#include <cuda_runtime.h>
#include <cuda_bf16.h>
#include <cstdint>

#define NN 50000
#define NF 128
#define NE 600000
#define NR 2
#define NSEG (NN * NR)          // 100000
#define SCAN_BLKS 98            // ceil(NSEG / 1024)
#define KP 1152                 // K' = 3 * 384 (split-precision concat)
#define NCH 18                  // 1152 / 64

// ---------------- scratch (device globals; no allocation allowed) ----------
__device__ float g_h[(size_t)NN * NF];
__device__ float g_stats[2 * NF];
__device__ int   g_deg[NSEG];
__device__ int   g_cursor[NSEG];
__device__ float g_icnt[NSEG];
__device__ int   g_csr[NE];
__device__ int   g_bsum[128];
// bf16 split operands
__device__ unsigned short g_hhi[(size_t)NN * NF];
__device__ unsigned short g_hlo[(size_t)NN * NF];
__device__ unsigned short g_mhi[(size_t)NN * NR * NF];
__device__ unsigned short g_mlo[(size_t)NN * NR * NF];
__device__ unsigned short g_wb[(size_t)4 * NF * KP];   // [layer][n=128][k'=1152]

// ---------------- helpers ---------------------------------------------------
__device__ __forceinline__ uint32_t smem_u32(const void* p) {
    uint32_t a;
    asm("{ .reg .u64 t; cvta.to.shared.u64 t, %1; cvt.u32.u64 %0, t; }"
        : "=r"(a) : "l"(p));
    return a;
}
#define SWZ128(off) ((off) ^ (((off) >> 3) & 0x70))
#define CP_ASYNC16(sm, gp) \
    asm volatile("cp.async.cg.shared.global [%0], [%1], 16;" :: "r"(sm), "l"(gp) : "memory")
#define CP_COMMIT() asm volatile("cp.async.commit_group;" ::: "memory")
#define CP_WAIT0()  asm volatile("cp.async.wait_group 0;" ::: "memory")

static __device__ __forceinline__ unsigned short bfu(float f) {
    __nv_bfloat16 b = __float2bfloat16(f);
    return *(unsigned short*)&b;
}
static __device__ __forceinline__ float bff(unsigned short u) {
    __nv_bfloat16 b = *(__nv_bfloat16*)&u;
    return __bfloat162float(b);
}
static __device__ __forceinline__ void split4(float4 v, uint2& hi, uint2& lo) {
    unsigned short hx = bfu(v.x), hy = bfu(v.y), hz = bfu(v.z), hw = bfu(v.w);
    unsigned short lx = bfu(v.x - bff(hx)), ly = bfu(v.y - bff(hy));
    unsigned short lz = bfu(v.z - bff(hz)), lw = bfu(v.w - bff(hw));
    hi.x = (uint32_t)hx | ((uint32_t)hy << 16);
    hi.y = (uint32_t)hz | ((uint32_t)hw << 16);
    lo.x = (uint32_t)lx | ((uint32_t)ly << 16);
    lo.y = (uint32_t)lz | ((uint32_t)lw << 16);
}

// ---------------------------------------------------------------------------
// CSR build (once per launch)
// ---------------------------------------------------------------------------
__global__ void hist_kernel(const int* __restrict__ dst, const int* __restrict__ et) {
    const int e = blockIdx.x * blockDim.x + threadIdx.x;
    if (e >= NE) return;
    atomicAdd(&g_deg[dst[e] * NR + et[e]], 1);
}
__global__ void scan1_kernel() {
    __shared__ int sh[256];
    const int t = threadIdx.x;
    const int base = blockIdx.x * 1024 + t * 4;
    int v[4];
#pragma unroll
    for (int k = 0; k < 4; k++) v[k] = (base + k < NSEG) ? g_deg[base + k] : 0;
    int sum = v[0] + v[1] + v[2] + v[3];
    sh[t] = sum;
    __syncthreads();
#pragma unroll
    for (int off = 1; off < 256; off <<= 1) {
        int add = (t >= off) ? sh[t - off] : 0;
        __syncthreads();
        sh[t] += add;
        __syncthreads();
    }
    int ex = sh[t] - sum;
#pragma unroll
    for (int k = 0; k < 4; k++) {
        if (base + k < NSEG) g_cursor[base + k] = ex;
        ex += v[k];
    }
    if (t == 255) g_bsum[blockIdx.x] = sh[255];
}
__global__ void scan2_kernel() {
    if (threadIdx.x == 0) {
        int a = 0;
        for (int i = 0; i < SCAN_BLKS; i++) { int v = g_bsum[i]; g_bsum[i] = a; a += v; }
    }
}
__global__ void addoff_kernel() {
    const int i = blockIdx.x * blockDim.x + threadIdx.x;
    if (i >= NSEG) return;
    g_cursor[i] += g_bsum[i >> 10];
    g_icnt[i] = 1.0f / (float)max(g_deg[i], 1);
}
__global__ void fill_kernel(const int* __restrict__ src, const int* __restrict__ dst,
                            const int* __restrict__ et) {
    const int e = blockIdx.x * blockDim.x + threadIdx.x;
    if (e >= NE) return;
    const int pos = atomicAdd(&g_cursor[dst[e] * NR + et[e]], 1);
    g_csr[pos] = src[e];
}

// ---------------------------------------------------------------------------
// Weight prep: g_wb[l][n][k'] for k'<384: hi; 384..767: hi; 768+: lo
// ---------------------------------------------------------------------------
__global__ void wt_kernel(const float* __restrict__ Wrel, const float* __restrict__ Wroot,
                          int layer) {
    const int i = blockIdx.x * blockDim.x + threadIdx.x;   // n*1152 + k'
    if (i >= NF * KP) return;
    const int n = i / KP;
    const int kp = i % KP;
    const int k = (kp < 384) ? kp : (kp < 768) ? (kp - 384) : (kp - 768);
    const float w = (k < 256) ? Wrel[k * NF + n] : Wroot[(k - 256) * NF + n];
    const unsigned short hi = bfu(w);
    g_wb[(size_t)layer * NF * KP + i] = (kp < 768) ? hi : bfu(w - bff(hi));
}

// ---------------------------------------------------------------------------
// Column stats for layer 0 input (later layers get stats from gemm epilogue)
// ---------------------------------------------------------------------------
__global__ void stats_kernel(const float* __restrict__ in) {
    __shared__ float ss[256], sq[256];
    const int tid = threadIdx.x;
    const int f = tid & 127;
    const int half = tid >> 7;
    float s = 0.f, s2 = 0.f;
    for (int r = blockIdx.x * 2 + half; r < NN; r += gridDim.x * 2) {
        float v = in[r * NF + f];
        s += v; s2 += v * v;
    }
    ss[tid] = s; sq[tid] = s2;
    __syncthreads();
    if (tid < 128) {
        atomicAdd(&g_stats[f], ss[tid] + ss[tid + 128]);
        atomicAdd(&g_stats[NF + f], sq[tid] + sq[tid + 128]);
    }
}

// ---------------------------------------------------------------------------
// BN normalize + split: writes bf16 hi/lo of BN(in) (root part of GEMM A)
// ---------------------------------------------------------------------------
__global__ void bn_kernel(const float* __restrict__ in) {
    const int i = blockIdx.x * blockDim.x + threadIdx.x;
    const int total = NN * NF / 4;
    if (i >= total) return;
    const int fb = (i * 4) & 127;
    const float4 v = ((const float4*)in)[i];
    const float invn = 1.0f / NN;
    float4 o;
    float mu, var, rs;
    mu = g_stats[fb + 0] * invn; var = g_stats[NF + fb + 0] * invn - mu * mu;
    rs = rsqrtf(var + 1e-5f); o.x = (v.x - mu) * rs + 1e-4f;
    mu = g_stats[fb + 1] * invn; var = g_stats[NF + fb + 1] * invn - mu * mu;
    rs = rsqrtf(var + 1e-5f); o.y = (v.y - mu) * rs + 1e-4f;
    mu = g_stats[fb + 2] * invn; var = g_stats[NF + fb + 2] * invn - mu * mu;
    rs = rsqrtf(var + 1e-5f); o.z = (v.z - mu) * rs + 1e-4f;
    mu = g_stats[fb + 3] * invn; var = g_stats[NF + fb + 3] * invn - mu * mu;
    rs = rsqrtf(var + 1e-5f); o.w = (v.w - mu) * rs + 1e-4f;
    uint2 hi, lo;
    split4(o, hi, lo);
    ((uint2*)g_hhi)[i] = hi;
    ((uint2*)g_hlo)[i] = lo;
}

// ---------------------------------------------------------------------------
// Gather aggregation: warp per (node, relation) segment on RAW input,
// csr ids prefetched warp-wide (breaks dependent-load chain), then BN affine
// applied to the mean (affine(mean) == mean(affine); deg==0 -> 0).
// ---------------------------------------------------------------------------
__global__ void agg_kernel(const float* __restrict__ in) {
    const int seg = (blockIdx.x * blockDim.x + threadIdx.x) >> 5;
    const int lane = threadIdx.x & 31;
    if (seg >= NSEG) return;
    const int end = g_cursor[seg];
    const int deg = g_deg[seg];
    const int start = end - deg;
    float4 acc = make_float4(0.f, 0.f, 0.f, 0.f);
    const float4* in4 = (const float4*)in;
    for (int base = start; base < end; base += 32) {
        const int nrem = end - base;
        const int cnt = (nrem < 32) ? nrem : 32;
        const int myid = (lane < cnt) ? __ldg(&g_csr[base + lane]) : 0;
#pragma unroll 2
        for (int e = 0; e < cnt; e++) {
            const int s = __shfl_sync(0xffffffffu, myid, e);
            const float4 v = in4[(size_t)s * 32 + lane];
            acc.x += v.x; acc.y += v.y; acc.z += v.z; acc.w += v.w;
        }
    }
    const float ic = g_icnt[seg];
    const float live = (deg > 0) ? 1.0f : 0.0f;
    const int f = lane * 4;
    const float invn = 1.0f / NN;
    const float4 st = *(const float4*)(g_stats + f);
    const float4 sq = *(const float4*)(g_stats + NF + f);
    float4 o;
    float mu, var, rs;
    mu = st.x * invn; var = sq.x * invn - mu * mu; rs = rsqrtf(var + 1e-5f);
    o.x = live * ((acc.x * ic - mu) * rs + 1e-4f);
    mu = st.y * invn; var = sq.y * invn - mu * mu; rs = rsqrtf(var + 1e-5f);
    o.y = live * ((acc.y * ic - mu) * rs + 1e-4f);
    mu = st.z * invn; var = sq.z * invn - mu * mu; rs = rsqrtf(var + 1e-5f);
    o.z = live * ((acc.z * ic - mu) * rs + 1e-4f);
    mu = st.w * invn; var = sq.w * invn - mu * mu; rs = rsqrtf(var + 1e-5f);
    o.w = live * ((acc.w * ic - mu) * rs + 1e-4f);
    uint2 hi, lo;
    split4(o, hi, lo);
    ((uint2*)g_mhi)[(size_t)seg * 32 + lane] = hi;
    ((uint2*)g_mlo)[(size_t)seg * 32 + lane] = lo;
}

// ---------------------------------------------------------------------------
// HMMA GEMM: out[128blk x 128] = A'[.,1152] B'^T, +bias, relu, +residual.
// Epilogue also accumulates next-layer BN column stats (sum, sumsq) if asked.
// ---------------------------------------------------------------------------
#define TILEB 16384
#define BUFB  (2 * TILEB)
#define SMEMB (2 * BUFB + 1024)

__global__ void __launch_bounds__(256, 2)
gemm_mma(const unsigned short* __restrict__ Wb, const float* __restrict__ bias,
         const float* __restrict__ res, float* __restrict__ out, int do_stats) {
    extern __shared__ char smraw[];
    __shared__ float s_stats[256];
    uint32_t sb0 = smem_u32(smraw);
    const uint32_t sb = (sb0 + 1023u) & ~1023u;

    const int tid = threadIdx.x;
    const int wid = tid >> 5;
    const int lane = tid & 31;
    const int rowBase = blockIdx.x * 128;

    s_stats[tid] = 0.f;   // ordered before use by pipeline __syncthreads

    const int r = tid >> 1;
    const int jb = (tid & 1) * 4;
    const int gnode = min(rowBase + r, NN - 1);
    const unsigned short* brow = Wb + (size_t)r * KP;

    const int warpM = wid >> 2;
    const int warpN = wid & 3;

    float acc[4][4][4];
#pragma unroll
    for (int mi = 0; mi < 4; mi++)
#pragma unroll
        for (int ni = 0; ni < 4; ni++)
#pragma unroll
            for (int q = 0; q < 4; q++) acc[mi][ni][q] = 0.f;

    const int a_row = warpM * 64 + ((lane >> 3) & 1) * 8 + (lane & 7);
    const int a_k8 = (lane >> 4) * 8;
    // B x4 addressing: pair p covers n-tiles 2p, 2p+1
    const int b_row = warpN * 32 + ((lane >> 4) & 1) * 8 + (lane & 7);
    const int b_k8 = ((lane >> 3) & 1) * 8;

#define LOAD_CHUNK(c, buf) do { \
        const uint32_t aB = sb + (buf) * BUFB; \
        const uint32_t bB = aB + TILEB; \
        const int part = ((c) >= 6 && (c) < 12) ? 1 : 0; \
        const int kc = (c) % 6; \
        const unsigned short* arow = (kc < 4) \
            ? (part ? g_mlo : g_mhi) + (size_t)gnode * 256 + kc * 64 \
            : (part ? g_hlo : g_hhi) + (size_t)gnode * 128 + (kc - 4) * 64; \
        const unsigned short* bsrc = brow + (c) * 64; \
        _Pragma("unroll") \
        for (int i = 0; i < 4; i++) { \
            const int j = jb + i; \
            const uint32_t sw = SWZ128(r * 128 + j * 16); \
            CP_ASYNC16(aB + sw, arow + j * 8); \
            CP_ASYNC16(bB + sw, bsrc + j * 8); \
        } \
        CP_COMMIT(); \
    } while (0)

    LOAD_CHUNK(0, 0);

#pragma unroll 1
    for (int c = 0; c < NCH; c++) {
        CP_WAIT0();
        __syncthreads();
        if (c + 1 < NCH) LOAD_CHUNK(c + 1, (c + 1) & 1);

        const uint32_t aB = sb + (c & 1) * BUFB;
        const uint32_t bB = aB + TILEB;
#pragma unroll
        for (int k16 = 0; k16 < 4; k16++) {
            uint32_t afr[4][4], bfr[4][2];
#pragma unroll
            for (int mi = 0; mi < 4; mi++) {
                const uint32_t addr = aB +
                    SWZ128((a_row + mi * 16) * 128 + (k16 * 16 + a_k8) * 2);
                asm volatile("ldmatrix.sync.aligned.m8n8.x4.shared.b16 "
                             "{%0,%1,%2,%3}, [%4];"
                             : "=r"(afr[mi][0]), "=r"(afr[mi][1]),
                               "=r"(afr[mi][2]), "=r"(afr[mi][3])
                             : "r"(addr));
            }
#pragma unroll
            for (int p = 0; p < 2; p++) {
                const uint32_t addr = bB +
                    SWZ128((b_row + p * 16) * 128 + (k16 * 16 + b_k8) * 2);
                asm volatile("ldmatrix.sync.aligned.m8n8.x4.shared.b16 "
                             "{%0,%1,%2,%3}, [%4];"
                             : "=r"(bfr[2 * p][0]), "=r"(bfr[2 * p][1]),
                               "=r"(bfr[2 * p + 1][0]), "=r"(bfr[2 * p + 1][1])
                             : "r"(addr));
            }
#pragma unroll
            for (int mi = 0; mi < 4; mi++)
#pragma unroll
                for (int ni = 0; ni < 4; ni++) {
                    asm volatile(
                        "mma.sync.aligned.m16n8k16.row.col.f32.bf16.bf16.f32 "
                        "{%0,%1,%2,%3}, {%4,%5,%6,%7}, {%8,%9}, {%0,%1,%2,%3};"
                        : "+f"(acc[mi][ni][0]), "+f"(acc[mi][ni][1]),
                          "+f"(acc[mi][ni][2]), "+f"(acc[mi][ni][3])
                        : "r"(afr[mi][0]), "r"(afr[mi][1]),
                          "r"(afr[mi][2]), "r"(afr[mi][3]),
                          "r"(bfr[ni][0]), "r"(bfr[ni][1]));
                }
        }
    }
#undef LOAD_CHUNK

    // ---- epilogue: +bias, relu, +residual, stats ----
    const int mBase = rowBase + warpM * 64 + (lane >> 2);
    const int nBase = warpN * 32 + (lane & 3) * 2;
#pragma unroll
    for (int ni = 0; ni < 4; ni++) {
        const int n0 = nBase + ni * 8;
        const float2 bv = *(const float2*)(bias + n0);
        float cs0 = 0.f, cs1 = 0.f, cq0 = 0.f, cq1 = 0.f;
#pragma unroll
        for (int mi = 0; mi < 4; mi++) {
#pragma unroll
            for (int h = 0; h < 2; h++) {
                const int m = mBase + mi * 16 + h * 8;
                if (m < NN) {
                    float2 o;
                    o.x = fmaxf(acc[mi][ni][h * 2 + 0] + bv.x, 0.f);
                    o.y = fmaxf(acc[mi][ni][h * 2 + 1] + bv.y, 0.f);
                    if (res) {
                        const float2 rv = *(const float2*)(res + (size_t)m * NF + n0);
                        o.x += rv.x; o.y += rv.y;
                    }
                    *(float2*)(out + (size_t)m * NF + n0) = o;
                    cs0 += o.x; cs1 += o.y;
                    cq0 += o.x * o.x; cq1 += o.y * o.y;
                }
            }
        }
        if (do_stats) {
            // reduce across lanes sharing the same column (lane>>2 varies)
#pragma unroll
            for (int off = 4; off < 32; off <<= 1) {
                cs0 += __shfl_xor_sync(0xffffffffu, cs0, off);
                cs1 += __shfl_xor_sync(0xffffffffu, cs1, off);
                cq0 += __shfl_xor_sync(0xffffffffu, cq0, off);
                cq1 += __shfl_xor_sync(0xffffffffu, cq1, off);
            }
            if ((lane >> 2) == 0) {
                atomicAdd(&s_stats[n0], cs0);
                atomicAdd(&s_stats[n0 + 1], cs1);
                atomicAdd(&s_stats[128 + n0], cq0);
                atomicAdd(&s_stats[128 + n0 + 1], cq1);
            }
        }
    }
    if (do_stats) {
        __syncthreads();
        atomicAdd(&g_stats[tid], s_stats[tid]);
    }
}

// ---------------------------------------------------------------------------
extern "C" void kernel_launch(void* const* d_in, const int* in_sizes, int n_in,
                              void* d_out, int out_size) {
    const float* x = (const float*)d_in[0];
    const int* ei = (const int*)d_in[1];
    const int* et = (const int*)d_in[2];
    const float* W0rel = (const float*)d_in[3];
    const float* W0root = (const float*)d_in[4];
    const float* b0 = (const float*)d_in[5];
    const float* Wsrel = (const float*)d_in[6];
    const float* Wsroot = (const float*)d_in[7];
    const float* bs = (const float*)d_in[8];
    float* outp = (float*)d_out;

    const int* src = ei;
    const int* dst = ei + NE;

    void *p_stats = 0, *p_h = 0, *p_deg = 0, *p_wb = 0;
    cudaGetSymbolAddress(&p_stats, g_stats);
    cudaGetSymbolAddress(&p_h, g_h);
    cudaGetSymbolAddress(&p_deg, g_deg);
    cudaGetSymbolAddress(&p_wb, g_wb);

    static int smem_set = 0;
    if (!smem_set) {
        cudaFuncSetAttribute(gemm_mma, cudaFuncAttributeMaxDynamicSharedMemorySize, SMEMB);
        smem_set = 1;
    }

    // ---- CSR build + weight prep (once per launch) ----
    cudaMemsetAsync(p_deg, 0, NSEG * sizeof(int));
    hist_kernel<<<(NE + 255) / 256, 256>>>(dst, et);
    scan1_kernel<<<SCAN_BLKS, 256>>>();
    scan2_kernel<<<1, 32>>>();
    addoff_kernel<<<(NSEG + 255) / 256, 256>>>();
    fill_kernel<<<(NE + 255) / 256, 256>>>(src, dst, et);
    for (int l = 0; l < 4; l++) {
        const float* Wrel = (l == 0) ? W0rel : Wsrel + (size_t)(l - 1) * NR * NF * NF;
        const float* Wroot = (l == 0) ? W0root : Wsroot + (size_t)(l - 1) * NF * NF;
        wt_kernel<<<(NF * KP + 255) / 256, 256>>>(Wrel, Wroot, l);
    }

    // layer-0 input stats
    cudaMemsetAsync(p_stats, 0, 2 * NF * sizeof(float));
    stats_kernel<<<256, 256>>>(x);

    // ---- layers ----
    for (int c = 0; c < 4; c++) {
        const float* in = (c == 0) ? x : (const float*)p_h;
        const float* bb = (c == 0) ? b0 : bs + (c - 1) * NF;
        const float* res = (c == 0) ? (const float*)0 : (const float*)p_h;
        float* o = (c == 3) ? outp : (float*)p_h;
        const unsigned short* wb = (const unsigned short*)p_wb + (size_t)c * NF * KP;
        const int do_stats = (c < 3) ? 1 : 0;

        bn_kernel<<<(NN * NF / 4 + 255) / 256, 256>>>(in);
        agg_kernel<<<(NSEG * 32 + 255) / 256, 256>>>(in);
        if (do_stats) cudaMemsetAsync(p_stats, 0, 2 * NF * sizeof(float));
        gemm_mma<<<(NN + 127) / 128, 256, SMEMB>>>(wb, bb, res, o, do_stats);
    }
}

// round 6
// speedup vs baseline: 2.5339x; 1.0266x over previous
#include <cuda_runtime.h>
#include <cuda_bf16.h>
#include <cstdint>

#define NN 50000
#define NF 128
#define NE 600000
#define NR 2
#define NSEG (NN * NR)          // 100000
#define SCAN_BLKS 98            // ceil(NSEG / 1024)
#define KP 1152                 // K' = 3 * 384 (split-precision concat)
#define NCH 18                  // 1152 / 64
#define BM 96                   // GEMM row tile
#define NBLK ((NN + BM - 1) / BM)   // 521

// ---------------- scratch (device globals; no allocation allowed) ----------
__device__ float g_h[(size_t)NN * NF];
__device__ float g_stats[2 * NF];
__device__ int   g_deg[NSEG];
__device__ int   g_cursor[NSEG];
__device__ float g_icnt[NSEG];
__device__ int   g_csr[NE];
__device__ int   g_bsum[128];
// bf16 split operands
__device__ unsigned short g_hhi[(size_t)NN * NF];
__device__ unsigned short g_hlo[(size_t)NN * NF];
__device__ unsigned short g_mhi[(size_t)NN * NR * NF];
__device__ unsigned short g_mlo[(size_t)NN * NR * NF];
__device__ unsigned short g_wb[(size_t)4 * NF * KP];   // [layer][n=128][k'=1152]

// ---------------- helpers ---------------------------------------------------
__device__ __forceinline__ uint32_t smem_u32(const void* p) {
    uint32_t a;
    asm("{ .reg .u64 t; cvta.to.shared.u64 t, %1; cvt.u32.u64 %0, t; }"
        : "=r"(a) : "l"(p));
    return a;
}
#define SWZ128(off) ((off) ^ (((off) >> 3) & 0x70))
#define CP_ASYNC16(sm, gp) \
    asm volatile("cp.async.cg.shared.global [%0], [%1], 16;" :: "r"(sm), "l"(gp) : "memory")
#define CP_COMMIT() asm volatile("cp.async.commit_group;" ::: "memory")
#define CP_WAIT0()  asm volatile("cp.async.wait_group 0;" ::: "memory")

static __device__ __forceinline__ unsigned short bfu(float f) {
    __nv_bfloat16 b = __float2bfloat16(f);
    return *(unsigned short*)&b;
}
static __device__ __forceinline__ float bff(unsigned short u) {
    __nv_bfloat16 b = *(__nv_bfloat16*)&u;
    return __bfloat162float(b);
}
static __device__ __forceinline__ void split4(float4 v, uint2& hi, uint2& lo) {
    unsigned short hx = bfu(v.x), hy = bfu(v.y), hz = bfu(v.z), hw = bfu(v.w);
    unsigned short lx = bfu(v.x - bff(hx)), ly = bfu(v.y - bff(hy));
    unsigned short lz = bfu(v.z - bff(hz)), lw = bfu(v.w - bff(hw));
    hi.x = (uint32_t)hx | ((uint32_t)hy << 16);
    hi.y = (uint32_t)hz | ((uint32_t)hw << 16);
    lo.x = (uint32_t)lx | ((uint32_t)ly << 16);
    lo.y = (uint32_t)lz | ((uint32_t)lw << 16);
}

// ---------------------------------------------------------------------------
// CSR build (once per launch)
// ---------------------------------------------------------------------------
__global__ void hist_kernel(const int* __restrict__ dst, const int* __restrict__ et) {
    const int e = blockIdx.x * blockDim.x + threadIdx.x;
    if (e >= NE) return;
    atomicAdd(&g_deg[dst[e] * NR + et[e]], 1);
}
__global__ void scan1_kernel() {
    __shared__ int sh[256];
    const int t = threadIdx.x;
    const int base = blockIdx.x * 1024 + t * 4;
    int v[4];
#pragma unroll
    for (int k = 0; k < 4; k++) v[k] = (base + k < NSEG) ? g_deg[base + k] : 0;
    int sum = v[0] + v[1] + v[2] + v[3];
    sh[t] = sum;
    __syncthreads();
#pragma unroll
    for (int off = 1; off < 256; off <<= 1) {
        int add = (t >= off) ? sh[t - off] : 0;
        __syncthreads();
        sh[t] += add;
        __syncthreads();
    }
    int ex = sh[t] - sum;
#pragma unroll
    for (int k = 0; k < 4; k++) {
        if (base + k < NSEG) g_cursor[base + k] = ex;
        ex += v[k];
    }
    if (t == 255) g_bsum[blockIdx.x] = sh[255];
}
__global__ void scan2_kernel() {
    if (threadIdx.x == 0) {
        int a = 0;
        for (int i = 0; i < SCAN_BLKS; i++) { int v = g_bsum[i]; g_bsum[i] = a; a += v; }
    }
}
__global__ void addoff_kernel() {
    const int i = blockIdx.x * blockDim.x + threadIdx.x;
    if (i >= NSEG) return;
    g_cursor[i] += g_bsum[i >> 10];
    g_icnt[i] = 1.0f / (float)max(g_deg[i], 1);
}
__global__ void fill_kernel(const int* __restrict__ src, const int* __restrict__ dst,
                            const int* __restrict__ et) {
    const int e = blockIdx.x * blockDim.x + threadIdx.x;
    if (e >= NE) return;
    const int pos = atomicAdd(&g_cursor[dst[e] * NR + et[e]], 1);
    g_csr[pos] = src[e];
}

// ---------------------------------------------------------------------------
// Weight prep: g_wb[l][n][k'] for k'<384: hi; 384..767: hi; 768+: lo
// ---------------------------------------------------------------------------
__global__ void wt_kernel(const float* __restrict__ Wrel, const float* __restrict__ Wroot,
                          int layer) {
    const int i = blockIdx.x * blockDim.x + threadIdx.x;   // n*1152 + k'
    if (i >= NF * KP) return;
    const int n = i / KP;
    const int kp = i % KP;
    const int k = (kp < 384) ? kp : (kp < 768) ? (kp - 384) : (kp - 768);
    const float w = (k < 256) ? Wrel[k * NF + n] : Wroot[(k - 256) * NF + n];
    const unsigned short hi = bfu(w);
    g_wb[(size_t)layer * NF * KP + i] = (kp < 768) ? hi : bfu(w - bff(hi));
}

// ---------------------------------------------------------------------------
// Column stats for layer 0 input (later layers: stats from gemm epilogue)
// ---------------------------------------------------------------------------
__global__ void stats_kernel(const float* __restrict__ in) {
    __shared__ float ss[256], sq[256];
    const int tid = threadIdx.x;
    const int f = tid & 127;
    const int half = tid >> 7;
    float s = 0.f, s2 = 0.f;
    for (int r = blockIdx.x * 2 + half; r < NN; r += gridDim.x * 2) {
        float v = in[r * NF + f];
        s += v; s2 += v * v;
    }
    ss[tid] = s; sq[tid] = s2;
    __syncthreads();
    if (tid < 128) {
        atomicAdd(&g_stats[f], ss[tid] + ss[tid + 128]);
        atomicAdd(&g_stats[NF + f], sq[tid] + sq[tid + 128]);
    }
}

// ---------------------------------------------------------------------------
// Fused aggregation + BN: warp per (node, relation) segment on RAW input.
// csr ids prefetched warp-wide; BN affine applied to the mean
// (affine(mean) == mean(affine); deg==0 -> 0). Warps with rel==0 also
// produce the BN hi/lo split of their own node's row (root GEMM operand).
// ---------------------------------------------------------------------------
__global__ void agg_kernel(const float* __restrict__ in) {
    const int seg = (blockIdx.x * blockDim.x + threadIdx.x) >> 5;
    const int lane = threadIdx.x & 31;
    if (seg >= NSEG) return;
    const int end = g_cursor[seg];
    const int deg = g_deg[seg];
    const int start = end - deg;
    float4 acc = make_float4(0.f, 0.f, 0.f, 0.f);
    const float4* in4 = (const float4*)in;
    for (int base = start; base < end; base += 32) {
        const int nrem = end - base;
        const int cnt = (nrem < 32) ? nrem : 32;
        const int myid = (lane < cnt) ? __ldg(&g_csr[base + lane]) : 0;
#pragma unroll 2
        for (int e = 0; e < cnt; e++) {
            const int s = __shfl_sync(0xffffffffu, myid, e);
            const float4 v = in4[(size_t)s * 32 + lane];
            acc.x += v.x; acc.y += v.y; acc.z += v.z; acc.w += v.w;
        }
    }
    const float ic = g_icnt[seg];
    const float live = (deg > 0) ? 1.0f : 0.0f;
    const int f = lane * 4;
    const float invn = 1.0f / NN;
    const float4 st = *(const float4*)(g_stats + f);
    const float4 sq = *(const float4*)(g_stats + NF + f);
    float mux, muy, muz, muw, rsx, rsy, rsz, rsw;
    mux = st.x * invn; rsx = rsqrtf(sq.x * invn - mux * mux + 1e-5f);
    muy = st.y * invn; rsy = rsqrtf(sq.y * invn - muy * muy + 1e-5f);
    muz = st.z * invn; rsz = rsqrtf(sq.z * invn - muz * muz + 1e-5f);
    muw = st.w * invn; rsw = rsqrtf(sq.w * invn - muw * muw + 1e-5f);

    float4 o;
    o.x = live * ((acc.x * ic - mux) * rsx + 1e-4f);
    o.y = live * ((acc.y * ic - muy) * rsy + 1e-4f);
    o.z = live * ((acc.z * ic - muz) * rsz + 1e-4f);
    o.w = live * ((acc.w * ic - muw) * rsw + 1e-4f);
    uint2 hi, lo;
    split4(o, hi, lo);
    ((uint2*)g_mhi)[(size_t)seg * 32 + lane] = hi;
    ((uint2*)g_mlo)[(size_t)seg * 32 + lane] = lo;

    if ((seg & 1) == 0) {
        // BN split of this node's own row (root operand)
        const int node = seg >> 1;
        const float4 v = in4[(size_t)node * 32 + lane];
        float4 r;
        r.x = (v.x - mux) * rsx + 1e-4f;
        r.y = (v.y - muy) * rsy + 1e-4f;
        r.z = (v.z - muz) * rsz + 1e-4f;
        r.w = (v.w - muw) * rsw + 1e-4f;
        uint2 rhi, rlo;
        split4(r, rhi, rlo);
        ((uint2*)g_hhi)[(size_t)node * 32 + lane] = rhi;
        ((uint2*)g_hlo)[(size_t)node * 32 + lane] = rlo;
    }
}

// ---------------------------------------------------------------------------
// HMMA GEMM: out[96blk x 128] = A'[.,1152] B'^T, +bias, relu, +residual.
// BM=96: 521 blocks -> better wave balance (2 waves x 0.75 tile-time).
// Warp layout: 2M x 4N, warp tile 48x32 (3 m16 x 4 n8).
// Epilogue also accumulates next-layer BN column stats if asked.
// ---------------------------------------------------------------------------
#define ATILEB (BM * 128)                     // 12288
#define BTILEB 16384
#define BUFB   (ATILEB + BTILEB)              // 28672
#define SMEMB  (2 * BUFB + 1024)

__global__ void __launch_bounds__(256, 2)
gemm_mma(const unsigned short* __restrict__ Wb, const float* __restrict__ bias,
         const float* __restrict__ res, float* __restrict__ out, int do_stats) {
    extern __shared__ char smraw[];
    __shared__ float s_stats[256];
    uint32_t sb0 = smem_u32(smraw);
    const uint32_t sb = (sb0 + 1023u) & ~1023u;

    const int tid = threadIdx.x;
    const int wid = tid >> 5;
    const int lane = tid & 31;
    const int rowBase = blockIdx.x * BM;

    s_stats[tid] = 0.f;

    // loader mapping: row r = tid/2, 4 x 16B pieces (A only for tid<192)
    const int r = tid >> 1;
    const int jb = (tid & 1) * 4;
    const int gnode = min(rowBase + r, NN - 1);
    const unsigned short* brow = Wb + (size_t)r * KP;

    const int warpM = wid >> 2;          // 0..1 -> 48 rows each
    const int warpN = wid & 3;           // 0..3 -> 32 cols each

    float acc[3][4][4];
#pragma unroll
    for (int mi = 0; mi < 3; mi++)
#pragma unroll
        for (int ni = 0; ni < 4; ni++)
#pragma unroll
            for (int q = 0; q < 4; q++) acc[mi][ni][q] = 0.f;

    const int a_row = warpM * 48 + ((lane >> 3) & 1) * 8 + (lane & 7);
    const int a_k8 = (lane >> 4) * 8;
    const int b_row = warpN * 32 + ((lane >> 4) & 1) * 8 + (lane & 7);
    const int b_k8 = ((lane >> 3) & 1) * 8;

#define LOAD_CHUNK(c, buf) do { \
        const uint32_t aB = sb + (buf) * BUFB; \
        const uint32_t bB = aB + ATILEB; \
        const int part = ((c) >= 6 && (c) < 12) ? 1 : 0; \
        const int kc = (c) % 6; \
        const unsigned short* arow = (kc < 4) \
            ? (part ? g_mlo : g_mhi) + (size_t)gnode * 256 + kc * 64 \
            : (part ? g_hlo : g_hhi) + (size_t)gnode * 128 + (kc - 4) * 64; \
        const unsigned short* bsrc = brow + (c) * 64; \
        if (tid < 192) { \
            _Pragma("unroll") \
            for (int i = 0; i < 4; i++) { \
                const int j = jb + i; \
                const uint32_t sw = SWZ128(r * 128 + j * 16); \
                CP_ASYNC16(aB + sw, arow + j * 8); \
            } \
        } \
        _Pragma("unroll") \
        for (int i = 0; i < 4; i++) { \
            const int j = jb + i; \
            const uint32_t sw = SWZ128(r * 128 + j * 16); \
            CP_ASYNC16(bB + sw, bsrc + j * 8); \
        } \
        CP_COMMIT(); \
    } while (0)

    LOAD_CHUNK(0, 0);

#pragma unroll 1
    for (int c = 0; c < NCH; c++) {
        CP_WAIT0();
        __syncthreads();
        if (c + 1 < NCH) LOAD_CHUNK(c + 1, (c + 1) & 1);

        const uint32_t aB = sb + (c & 1) * BUFB;
        const uint32_t bB = aB + ATILEB;
#pragma unroll
        for (int k16 = 0; k16 < 4; k16++) {
            uint32_t afr[3][4], bfr[4][2];
#pragma unroll
            for (int mi = 0; mi < 3; mi++) {
                const uint32_t addr = aB +
                    SWZ128((a_row + mi * 16) * 128 + (k16 * 16 + a_k8) * 2);
                asm volatile("ldmatrix.sync.aligned.m8n8.x4.shared.b16 "
                             "{%0,%1,%2,%3}, [%4];"
                             : "=r"(afr[mi][0]), "=r"(afr[mi][1]),
                               "=r"(afr[mi][2]), "=r"(afr[mi][3])
                             : "r"(addr));
            }
#pragma unroll
            for (int p = 0; p < 2; p++) {
                const uint32_t addr = bB +
                    SWZ128((b_row + p * 16) * 128 + (k16 * 16 + b_k8) * 2);
                asm volatile("ldmatrix.sync.aligned.m8n8.x4.shared.b16 "
                             "{%0,%1,%2,%3}, [%4];"
                             : "=r"(bfr[2 * p][0]), "=r"(bfr[2 * p][1]),
                               "=r"(bfr[2 * p + 1][0]), "=r"(bfr[2 * p + 1][1])
                             : "r"(addr));
            }
#pragma unroll
            for (int mi = 0; mi < 3; mi++)
#pragma unroll
                for (int ni = 0; ni < 4; ni++) {
                    asm volatile(
                        "mma.sync.aligned.m16n8k16.row.col.f32.bf16.bf16.f32 "
                        "{%0,%1,%2,%3}, {%4,%5,%6,%7}, {%8,%9}, {%0,%1,%2,%3};"
                        : "+f"(acc[mi][ni][0]), "+f"(acc[mi][ni][1]),
                          "+f"(acc[mi][ni][2]), "+f"(acc[mi][ni][3])
                        : "r"(afr[mi][0]), "r"(afr[mi][1]),
                          "r"(afr[mi][2]), "r"(afr[mi][3]),
                          "r"(bfr[ni][0]), "r"(bfr[ni][1]));
                }
        }
    }
#undef LOAD_CHUNK

    // ---- epilogue: +bias, relu, +residual, stats ----
    const int mBase = rowBase + warpM * 48 + (lane >> 2);
    const int nBase = warpN * 32 + (lane & 3) * 2;
#pragma unroll
    for (int ni = 0; ni < 4; ni++) {
        const int n0 = nBase + ni * 8;
        const float2 bv = *(const float2*)(bias + n0);
        float cs0 = 0.f, cs1 = 0.f, cq0 = 0.f, cq1 = 0.f;
#pragma unroll
        for (int mi = 0; mi < 3; mi++) {
#pragma unroll
            for (int h = 0; h < 2; h++) {
                const int m = mBase + mi * 16 + h * 8;
                if (m < NN) {
                    float2 o;
                    o.x = fmaxf(acc[mi][ni][h * 2 + 0] + bv.x, 0.f);
                    o.y = fmaxf(acc[mi][ni][h * 2 + 1] + bv.y, 0.f);
                    if (res) {
                        const float2 rv = *(const float2*)(res + (size_t)m * NF + n0);
                        o.x += rv.x; o.y += rv.y;
                    }
                    *(float2*)(out + (size_t)m * NF + n0) = o;
                    cs0 += o.x; cs1 += o.y;
                    cq0 += o.x * o.x; cq1 += o.y * o.y;
                }
            }
        }
        if (do_stats) {
#pragma unroll
            for (int off = 4; off < 32; off <<= 1) {
                cs0 += __shfl_xor_sync(0xffffffffu, cs0, off);
                cs1 += __shfl_xor_sync(0xffffffffu, cs1, off);
                cq0 += __shfl_xor_sync(0xffffffffu, cq0, off);
                cq1 += __shfl_xor_sync(0xffffffffu, cq1, off);
            }
            if ((lane >> 2) == 0) {
                atomicAdd(&s_stats[n0], cs0);
                atomicAdd(&s_stats[n0 + 1], cs1);
                atomicAdd(&s_stats[128 + n0], cq0);
                atomicAdd(&s_stats[128 + n0 + 1], cq1);
            }
        }
    }
    if (do_stats) {
        __syncthreads();
        atomicAdd(&g_stats[tid], s_stats[tid]);
    }
}

// ---------------------------------------------------------------------------
extern "C" void kernel_launch(void* const* d_in, const int* in_sizes, int n_in,
                              void* d_out, int out_size) {
    const float* x = (const float*)d_in[0];
    const int* ei = (const int*)d_in[1];
    const int* et = (const int*)d_in[2];
    const float* W0rel = (const float*)d_in[3];
    const float* W0root = (const float*)d_in[4];
    const float* b0 = (const float*)d_in[5];
    const float* Wsrel = (const float*)d_in[6];
    const float* Wsroot = (const float*)d_in[7];
    const float* bs = (const float*)d_in[8];
    float* outp = (float*)d_out;

    const int* src = ei;
    const int* dst = ei + NE;

    void *p_stats = 0, *p_h = 0, *p_deg = 0, *p_wb = 0;
    cudaGetSymbolAddress(&p_stats, g_stats);
    cudaGetSymbolAddress(&p_h, g_h);
    cudaGetSymbolAddress(&p_deg, g_deg);
    cudaGetSymbolAddress(&p_wb, g_wb);

    static int smem_set = 0;
    if (!smem_set) {
        cudaFuncSetAttribute(gemm_mma, cudaFuncAttributeMaxDynamicSharedMemorySize, SMEMB);
        smem_set = 1;
    }

    // ---- CSR build + weight prep (once per launch) ----
    cudaMemsetAsync(p_deg, 0, NSEG * sizeof(int));
    hist_kernel<<<(NE + 255) / 256, 256>>>(dst, et);
    scan1_kernel<<<SCAN_BLKS, 256>>>();
    scan2_kernel<<<1, 32>>>();
    addoff_kernel<<<(NSEG + 255) / 256, 256>>>();
    fill_kernel<<<(NE + 255) / 256, 256>>>(src, dst, et);
    for (int l = 0; l < 4; l++) {
        const float* Wrel = (l == 0) ? W0rel : Wsrel + (size_t)(l - 1) * NR * NF * NF;
        const float* Wroot = (l == 0) ? W0root : Wsroot + (size_t)(l - 1) * NF * NF;
        wt_kernel<<<(NF * KP + 255) / 256, 256>>>(Wrel, Wroot, l);
    }

    // layer-0 input stats
    cudaMemsetAsync(p_stats, 0, 2 * NF * sizeof(float));
    stats_kernel<<<256, 256>>>(x);

    // ---- layers ----
    for (int c = 0; c < 4; c++) {
        const float* in = (c == 0) ? x : (const float*)p_h;
        const float* bb = (c == 0) ? b0 : bs + (c - 1) * NF;
        const float* res = (c == 0) ? (const float*)0 : (const float*)p_h;
        float* o = (c == 3) ? outp : (float*)p_h;
        const unsigned short* wb = (const unsigned short*)p_wb + (size_t)c * NF * KP;
        const int do_stats = (c < 3) ? 1 : 0;

        agg_kernel<<<(NSEG * 32 + 255) / 256, 256>>>(in);
        if (do_stats) cudaMemsetAsync(p_stats, 0, 2 * NF * sizeof(float));
        gemm_mma<<<NBLK, 256, SMEMB>>>(wb, bb, res, o, do_stats);
    }
}

// round 7
// speedup vs baseline: 2.7028x; 1.0667x over previous
#include <cuda_runtime.h>
#include <cuda_bf16.h>
#include <cstdint>

#define NN 50000
#define NF 128
#define NE 600000
#define NR 2
#define NSEG (NN * NR)          // 100000
#define SCAN_BLKS 98            // ceil(NSEG / 1024)
#define KP 1152                 // K' = 3 * 384 (split-precision concat)
#define NCH 18                  // 1152 / 64

// ---------------- scratch (device globals; no allocation allowed) ----------
__device__ float g_h[(size_t)NN * NF];
__device__ float g_stats[2 * NF];
__device__ int   g_deg[NSEG];
__device__ int   g_cursor[NSEG];
__device__ float g_icnt[NSEG];
__device__ int   g_csr[NE];
__device__ int   g_bsum[128];
// bf16 split operands
__device__ unsigned short g_hhi[(size_t)NN * NF];
__device__ unsigned short g_hlo[(size_t)NN * NF];
__device__ unsigned short g_mhi[(size_t)NN * NR * NF];
__device__ unsigned short g_mlo[(size_t)NN * NR * NF];
__device__ unsigned short g_wb[(size_t)4 * NF * KP];   // [layer][n=128][k'=1152]

// ---------------- helpers ---------------------------------------------------
__device__ __forceinline__ uint32_t smem_u32(const void* p) {
    uint32_t a;
    asm("{ .reg .u64 t; cvta.to.shared.u64 t, %1; cvt.u32.u64 %0, t; }"
        : "=r"(a) : "l"(p));
    return a;
}
#define SWZ128(off) ((off) ^ (((off) >> 3) & 0x70))
#define CP_ASYNC16(sm, gp) \
    asm volatile("cp.async.cg.shared.global [%0], [%1], 16;" :: "r"(sm), "l"(gp) : "memory")
#define CP_COMMIT() asm volatile("cp.async.commit_group;" ::: "memory")
#define CP_WAIT0()  asm volatile("cp.async.wait_group 0;" ::: "memory")

static __device__ __forceinline__ unsigned short bfu(float f) {
    __nv_bfloat16 b = __float2bfloat16(f);
    return *(unsigned short*)&b;
}
static __device__ __forceinline__ float bff(unsigned short u) {
    __nv_bfloat16 b = *(__nv_bfloat16*)&u;
    return __bfloat162float(b);
}
static __device__ __forceinline__ void split4(float4 v, uint2& hi, uint2& lo) {
    unsigned short hx = bfu(v.x), hy = bfu(v.y), hz = bfu(v.z), hw = bfu(v.w);
    unsigned short lx = bfu(v.x - bff(hx)), ly = bfu(v.y - bff(hy));
    unsigned short lz = bfu(v.z - bff(hz)), lw = bfu(v.w - bff(hw));
    hi.x = (uint32_t)hx | ((uint32_t)hy << 16);
    hi.y = (uint32_t)hz | ((uint32_t)hw << 16);
    lo.x = (uint32_t)lx | ((uint32_t)ly << 16);
    lo.y = (uint32_t)lz | ((uint32_t)lw << 16);
}

// ---------------------------------------------------------------------------
// CSR build (once per launch)
// ---------------------------------------------------------------------------
__global__ void hist_kernel(const int* __restrict__ dst, const int* __restrict__ et) {
    const int e = blockIdx.x * blockDim.x + threadIdx.x;
    if (e >= NE) return;
    atomicAdd(&g_deg[dst[e] * NR + et[e]], 1);
}
__global__ void scan1_kernel() {
    __shared__ int sh[256];
    const int t = threadIdx.x;
    const int base = blockIdx.x * 1024 + t * 4;
    int v[4];
#pragma unroll
    for (int k = 0; k < 4; k++) v[k] = (base + k < NSEG) ? g_deg[base + k] : 0;
    int sum = v[0] + v[1] + v[2] + v[3];
    sh[t] = sum;
    __syncthreads();
#pragma unroll
    for (int off = 1; off < 256; off <<= 1) {
        int add = (t >= off) ? sh[t - off] : 0;
        __syncthreads();
        sh[t] += add;
        __syncthreads();
    }
    int ex = sh[t] - sum;
#pragma unroll
    for (int k = 0; k < 4; k++) {
        if (base + k < NSEG) g_cursor[base + k] = ex;
        ex += v[k];
    }
    if (t == 255) g_bsum[blockIdx.x] = sh[255];
}
__global__ void scan2_kernel() {
    if (threadIdx.x == 0) {
        int a = 0;
        for (int i = 0; i < SCAN_BLKS; i++) { int v = g_bsum[i]; g_bsum[i] = a; a += v; }
    }
}
__global__ void addoff_kernel() {
    const int i = blockIdx.x * blockDim.x + threadIdx.x;
    if (i >= NSEG) return;
    g_cursor[i] += g_bsum[i >> 10];
    g_icnt[i] = 1.0f / (float)max(g_deg[i], 1);
}
__global__ void fill_kernel(const int* __restrict__ src, const int* __restrict__ dst,
                            const int* __restrict__ et) {
    const int e = blockIdx.x * blockDim.x + threadIdx.x;
    if (e >= NE) return;
    const int pos = atomicAdd(&g_cursor[dst[e] * NR + et[e]], 1);
    g_csr[pos] = src[e];
}

// ---------------------------------------------------------------------------
// Weight prep (all 4 layers in one launch):
// g_wb[l][n][k'] for k'<384: hi; 384..767: hi; 768+: lo
// ---------------------------------------------------------------------------
__global__ void wt_kernel(const float* __restrict__ W0rel, const float* __restrict__ W0root,
                          const float* __restrict__ Wsrel, const float* __restrict__ Wsroot) {
    const int gi = blockIdx.x * blockDim.x + threadIdx.x;  // l*NF*KP + n*KP + k'
    if (gi >= 4 * NF * KP) return;
    const int l = gi / (NF * KP);
    const int i = gi % (NF * KP);
    const int n = i / KP;
    const int kp = i % KP;
    const int k = (kp < 384) ? kp : (kp < 768) ? (kp - 384) : (kp - 768);
    const float* Wrel = (l == 0) ? W0rel : Wsrel + (size_t)(l - 1) * NR * NF * NF;
    const float* Wroot = (l == 0) ? W0root : Wsroot + (size_t)(l - 1) * NF * NF;
    const float w = (k < 256) ? Wrel[k * NF + n] : Wroot[(k - 256) * NF + n];
    const unsigned short hi = bfu(w);
    g_wb[gi] = (kp < 768) ? hi : bfu(w - bff(hi));
}

// ---------------------------------------------------------------------------
// Column stats for layer 0 input (later layers: stats from gemm epilogue)
// ---------------------------------------------------------------------------
__global__ void stats_kernel(const float* __restrict__ in) {
    __shared__ float ss[256], sq[256];
    const int tid = threadIdx.x;
    const int f = tid & 127;
    const int half = tid >> 7;
    float s = 0.f, s2 = 0.f;
    for (int r = blockIdx.x * 2 + half; r < NN; r += gridDim.x * 2) {
        float v = in[r * NF + f];
        s += v; s2 += v * v;
    }
    ss[tid] = s; sq[tid] = s2;
    __syncthreads();
    if (tid < 128) {
        atomicAdd(&g_stats[f], ss[tid] + ss[tid + 128]);
        atomicAdd(&g_stats[NF + f], sq[tid] + sq[tid + 128]);
    }
}

// ---------------------------------------------------------------------------
// Fused aggregation + BN: warp per (node, relation) segment on RAW input.
// 4-wide independent gathers (MLP), BN affine applied to the mean
// (affine(mean) == mean(affine); deg==0 -> 0). rel==0 warps also produce the
// BN hi/lo split of their own node's row (root GEMM operand).
// ---------------------------------------------------------------------------
__global__ void agg_kernel(const float* __restrict__ in) {
    const int seg = (blockIdx.x * blockDim.x + threadIdx.x) >> 5;
    const int lane = threadIdx.x & 31;
    if (seg >= NSEG) return;
    const int end = g_cursor[seg];
    const int deg = g_deg[seg];
    const int start = end - deg;
    float4 acc = make_float4(0.f, 0.f, 0.f, 0.f);
    const float4* in4 = (const float4*)in;
    for (int base = start; base < end; base += 32) {
        const int nrem = end - base;
        const int cnt = (nrem < 32) ? nrem : 32;
        const int myid = (lane < cnt) ? __ldg(&g_csr[base + lane]) : 0;
        int e = 0;
        for (; e + 4 <= cnt; e += 4) {
            const int s0 = __shfl_sync(0xffffffffu, myid, e + 0);
            const int s1 = __shfl_sync(0xffffffffu, myid, e + 1);
            const int s2 = __shfl_sync(0xffffffffu, myid, e + 2);
            const int s3 = __shfl_sync(0xffffffffu, myid, e + 3);
            const float4 v0 = in4[(size_t)s0 * 32 + lane];
            const float4 v1 = in4[(size_t)s1 * 32 + lane];
            const float4 v2 = in4[(size_t)s2 * 32 + lane];
            const float4 v3 = in4[(size_t)s3 * 32 + lane];
            acc.x += v0.x + v1.x + v2.x + v3.x;
            acc.y += v0.y + v1.y + v2.y + v3.y;
            acc.z += v0.z + v1.z + v2.z + v3.z;
            acc.w += v0.w + v1.w + v2.w + v3.w;
        }
        for (; e < cnt; e++) {
            const int s = __shfl_sync(0xffffffffu, myid, e);
            const float4 v = in4[(size_t)s * 32 + lane];
            acc.x += v.x; acc.y += v.y; acc.z += v.z; acc.w += v.w;
        }
    }
    const float ic = g_icnt[seg];
    const float live = (deg > 0) ? 1.0f : 0.0f;
    const int f = lane * 4;
    const float invn = 1.0f / NN;
    const float4 st = *(const float4*)(g_stats + f);
    const float4 sq = *(const float4*)(g_stats + NF + f);
    float mux, muy, muz, muw, rsx, rsy, rsz, rsw;
    mux = st.x * invn; rsx = rsqrtf(sq.x * invn - mux * mux + 1e-5f);
    muy = st.y * invn; rsy = rsqrtf(sq.y * invn - muy * muy + 1e-5f);
    muz = st.z * invn; rsz = rsqrtf(sq.z * invn - muz * muz + 1e-5f);
    muw = st.w * invn; rsw = rsqrtf(sq.w * invn - muw * muw + 1e-5f);

    float4 o;
    o.x = live * ((acc.x * ic - mux) * rsx + 1e-4f);
    o.y = live * ((acc.y * ic - muy) * rsy + 1e-4f);
    o.z = live * ((acc.z * ic - muz) * rsz + 1e-4f);
    o.w = live * ((acc.w * ic - muw) * rsw + 1e-4f);
    uint2 hi, lo;
    split4(o, hi, lo);
    ((uint2*)g_mhi)[(size_t)seg * 32 + lane] = hi;
    ((uint2*)g_mlo)[(size_t)seg * 32 + lane] = lo;

    if ((seg & 1) == 0) {
        const int node = seg >> 1;
        const float4 v = in4[(size_t)node * 32 + lane];
        float4 r;
        r.x = (v.x - mux) * rsx + 1e-4f;
        r.y = (v.y - muy) * rsy + 1e-4f;
        r.z = (v.z - muz) * rsz + 1e-4f;
        r.w = (v.w - muw) * rsw + 1e-4f;
        uint2 rhi, rlo;
        split4(r, rhi, rlo);
        ((uint2*)g_hhi)[(size_t)node * 32 + lane] = rhi;
        ((uint2*)g_hlo)[(size_t)node * 32 + lane] = rlo;
    }
}

// ---------------------------------------------------------------------------
// HMMA GEMM: out[128blk x 128] = A'[.,1152] B'^T, +bias, relu, +residual.
// 8 warps (2M x 4N), warp tile 64x32, cp.async double-buffered K=64 chunks.
// Epilogue also accumulates next-layer BN column stats if asked.
// ---------------------------------------------------------------------------
#define TILEB 16384
#define BUFB  (2 * TILEB)
#define SMEMB (2 * BUFB + 1024)

__global__ void __launch_bounds__(256, 2)
gemm_mma(const unsigned short* __restrict__ Wb, const float* __restrict__ bias,
         const float* __restrict__ res, float* __restrict__ out, int do_stats) {
    extern __shared__ char smraw[];
    __shared__ float s_stats[256];
    uint32_t sb0 = smem_u32(smraw);
    const uint32_t sb = (sb0 + 1023u) & ~1023u;

    const int tid = threadIdx.x;
    const int wid = tid >> 5;
    const int lane = tid & 31;
    const int rowBase = blockIdx.x * 128;

    s_stats[tid] = 0.f;

    const int r = tid >> 1;
    const int jb = (tid & 1) * 4;
    const int gnode = min(rowBase + r, NN - 1);
    const unsigned short* brow = Wb + (size_t)r * KP;

    const int warpM = wid >> 2;
    const int warpN = wid & 3;

    float acc[4][4][4];
#pragma unroll
    for (int mi = 0; mi < 4; mi++)
#pragma unroll
        for (int ni = 0; ni < 4; ni++)
#pragma unroll
            for (int q = 0; q < 4; q++) acc[mi][ni][q] = 0.f;

    const int a_row = warpM * 64 + ((lane >> 3) & 1) * 8 + (lane & 7);
    const int a_k8 = (lane >> 4) * 8;
    const int b_row = warpN * 32 + ((lane >> 4) & 1) * 8 + (lane & 7);
    const int b_k8 = ((lane >> 3) & 1) * 8;

#define LOAD_CHUNK(c, buf) do { \
        const uint32_t aB = sb + (buf) * BUFB; \
        const uint32_t bB = aB + TILEB; \
        const int part = ((c) >= 6 && (c) < 12) ? 1 : 0; \
        const int kc = (c) % 6; \
        const unsigned short* arow = (kc < 4) \
            ? (part ? g_mlo : g_mhi) + (size_t)gnode * 256 + kc * 64 \
            : (part ? g_hlo : g_hhi) + (size_t)gnode * 128 + (kc - 4) * 64; \
        const unsigned short* bsrc = brow + (c) * 64; \
        _Pragma("unroll") \
        for (int i = 0; i < 4; i++) { \
            const int j = jb + i; \
            const uint32_t sw = SWZ128(r * 128 + j * 16); \
            CP_ASYNC16(aB + sw, arow + j * 8); \
            CP_ASYNC16(bB + sw, bsrc + j * 8); \
        } \
        CP_COMMIT(); \
    } while (0)

    LOAD_CHUNK(0, 0);

#pragma unroll 1
    for (int c = 0; c < NCH; c++) {
        CP_WAIT0();
        __syncthreads();
        if (c + 1 < NCH) LOAD_CHUNK(c + 1, (c + 1) & 1);

        const uint32_t aB = sb + (c & 1) * BUFB;
        const uint32_t bB = aB + TILEB;
#pragma unroll
        for (int k16 = 0; k16 < 4; k16++) {
            uint32_t afr[4][4], bfr[4][2];
#pragma unroll
            for (int mi = 0; mi < 4; mi++) {
                const uint32_t addr = aB +
                    SWZ128((a_row + mi * 16) * 128 + (k16 * 16 + a_k8) * 2);
                asm volatile("ldmatrix.sync.aligned.m8n8.x4.shared.b16 "
                             "{%0,%1,%2,%3}, [%4];"
                             : "=r"(afr[mi][0]), "=r"(afr[mi][1]),
                               "=r"(afr[mi][2]), "=r"(afr[mi][3])
                             : "r"(addr));
            }
#pragma unroll
            for (int p = 0; p < 2; p++) {
                const uint32_t addr = bB +
                    SWZ128((b_row + p * 16) * 128 + (k16 * 16 + b_k8) * 2);
                asm volatile("ldmatrix.sync.aligned.m8n8.x4.shared.b16 "
                             "{%0,%1,%2,%3}, [%4];"
                             : "=r"(bfr[2 * p][0]), "=r"(bfr[2 * p][1]),
                               "=r"(bfr[2 * p + 1][0]), "=r"(bfr[2 * p + 1][1])
                             : "r"(addr));
            }
#pragma unroll
            for (int mi = 0; mi < 4; mi++)
#pragma unroll
                for (int ni = 0; ni < 4; ni++) {
                    asm volatile(
                        "mma.sync.aligned.m16n8k16.row.col.f32.bf16.bf16.f32 "
                        "{%0,%1,%2,%3}, {%4,%5,%6,%7}, {%8,%9}, {%0,%1,%2,%3};"
                        : "+f"(acc[mi][ni][0]), "+f"(acc[mi][ni][1]),
                          "+f"(acc[mi][ni][2]), "+f"(acc[mi][ni][3])
                        : "r"(afr[mi][0]), "r"(afr[mi][1]),
                          "r"(afr[mi][2]), "r"(afr[mi][3]),
                          "r"(bfr[ni][0]), "r"(bfr[ni][1]));
                }
        }
    }
#undef LOAD_CHUNK

    // ---- epilogue: +bias, relu, +residual, stats ----
    const int mBase = rowBase + warpM * 64 + (lane >> 2);
    const int nBase = warpN * 32 + (lane & 3) * 2;
#pragma unroll
    for (int ni = 0; ni < 4; ni++) {
        const int n0 = nBase + ni * 8;
        const float2 bv = *(const float2*)(bias + n0);
        float cs0 = 0.f, cs1 = 0.f, cq0 = 0.f, cq1 = 0.f;
#pragma unroll
        for (int mi = 0; mi < 4; mi++) {
#pragma unroll
            for (int h = 0; h < 2; h++) {
                const int m = mBase + mi * 16 + h * 8;
                if (m < NN) {
                    float2 o;
                    o.x = fmaxf(acc[mi][ni][h * 2 + 0] + bv.x, 0.f);
                    o.y = fmaxf(acc[mi][ni][h * 2 + 1] + bv.y, 0.f);
                    if (res) {
                        const float2 rv = *(const float2*)(res + (size_t)m * NF + n0);
                        o.x += rv.x; o.y += rv.y;
                    }
                    *(float2*)(out + (size_t)m * NF + n0) = o;
                    cs0 += o.x; cs1 += o.y;
                    cq0 += o.x * o.x; cq1 += o.y * o.y;
                }
            }
        }
        if (do_stats) {
#pragma unroll
            for (int off = 4; off < 32; off <<= 1) {
                cs0 += __shfl_xor_sync(0xffffffffu, cs0, off);
                cs1 += __shfl_xor_sync(0xffffffffu, cs1, off);
                cq0 += __shfl_xor_sync(0xffffffffu, cq0, off);
                cq1 += __shfl_xor_sync(0xffffffffu, cq1, off);
            }
            if ((lane >> 2) == 0) {
                atomicAdd(&s_stats[n0], cs0);
                atomicAdd(&s_stats[n0 + 1], cs1);
                atomicAdd(&s_stats[128 + n0], cq0);
                atomicAdd(&s_stats[128 + n0 + 1], cq1);
            }
        }
    }
    if (do_stats) {
        __syncthreads();
        atomicAdd(&g_stats[tid], s_stats[tid]);
    }
}

// ---------------------------------------------------------------------------
extern "C" void kernel_launch(void* const* d_in, const int* in_sizes, int n_in,
                              void* d_out, int out_size) {
    const float* x = (const float*)d_in[0];
    const int* ei = (const int*)d_in[1];
    const int* et = (const int*)d_in[2];
    const float* W0rel = (const float*)d_in[3];
    const float* W0root = (const float*)d_in[4];
    const float* b0 = (const float*)d_in[5];
    const float* Wsrel = (const float*)d_in[6];
    const float* Wsroot = (const float*)d_in[7];
    const float* bs = (const float*)d_in[8];
    float* outp = (float*)d_out;

    const int* src = ei;
    const int* dst = ei + NE;

    void *p_stats = 0, *p_h = 0, *p_deg = 0, *p_wb = 0;
    cudaGetSymbolAddress(&p_stats, g_stats);
    cudaGetSymbolAddress(&p_h, g_h);
    cudaGetSymbolAddress(&p_deg, g_deg);
    cudaGetSymbolAddress(&p_wb, g_wb);

    static int smem_set = 0;
    if (!smem_set) {
        cudaFuncSetAttribute(gemm_mma, cudaFuncAttributeMaxDynamicSharedMemorySize, SMEMB);
        smem_set = 1;
    }

    // ---- CSR build + weight prep (once per launch) ----
    cudaMemsetAsync(p_deg, 0, NSEG * sizeof(int));
    hist_kernel<<<(NE + 255) / 256, 256>>>(dst, et);
    scan1_kernel<<<SCAN_BLKS, 256>>>();
    scan2_kernel<<<1, 32>>>();
    addoff_kernel<<<(NSEG + 255) / 256, 256>>>();
    fill_kernel<<<(NE + 255) / 256, 256>>>(src, dst, et);
    wt_kernel<<<(4 * NF * KP + 255) / 256, 256>>>(W0rel, W0root, Wsrel, Wsroot);

    // layer-0 input stats
    cudaMemsetAsync(p_stats, 0, 2 * NF * sizeof(float));
    stats_kernel<<<256, 256>>>(x);

    // ---- layers ----
    for (int c = 0; c < 4; c++) {
        const float* in = (c == 0) ? x : (const float*)p_h;
        const float* bb = (c == 0) ? b0 : bs + (c - 1) * NF;
        const float* res = (c == 0) ? (const float*)0 : (const float*)p_h;
        float* o = (c == 3) ? outp : (float*)p_h;
        const unsigned short* wb = (const unsigned short*)p_wb + (size_t)c * NF * KP;
        const int do_stats = (c < 3) ? 1 : 0;

        agg_kernel<<<(NSEG * 32 + 255) / 256, 256>>>(in);
        if (do_stats) cudaMemsetAsync(p_stats, 0, 2 * NF * sizeof(float));
        gemm_mma<<<(NN + 127) / 128, 256, SMEMB>>>(wb, bb, res, o, do_stats);
    }
}